// round 9
// baseline (speedup 1.0000x reference)
#include <cuda_runtime.h>
#include <cuda_fp16.h>
#include <cstdint>
#include <cstddef>

#define NUMNODES 32768
#define NCHAIN   1024

// -------- global scratch (no allocations allowed) --------
__device__ __half g_ymsg[(size_t)NUMNODES * 1024];   // 64 MB msg buffer (fp16)
__device__ float  g_yself[(size_t)NUMNODES * 128];   // 16 MB self buffer (fp32)
__device__ float  g_alpha[(size_t)NUMNODES * 16];
__device__ float  g_bufA[(size_t)NUMNODES * 128];
__device__ float  g_bufB[(size_t)NUMNODES * 128];
__device__ __half g_xh[(size_t)NUMNODES * 128];      // split activations (fp16)
__device__ __half g_xl[(size_t)NUMNODES * 128];
#define WSLOT (1152 * 128)
__device__ __half g_w16[3 * WSLOT];                  // single fp16 weights [n][k]
__device__ float g_bias[3 * 1152];

// ================= PTX helpers (baseline ISA only) =================
__device__ __forceinline__ uint32_t smem_u32(const void* p) {
    uint32_t a;
    asm("{ .reg .u64 t; cvta.to.shared.u64 t, %1; cvt.u32.u64 %0, t; }" : "=r"(a) : "l"(p));
    return a;
}
__device__ __forceinline__ void cp16(uint32_t dst, const void* src) {
    asm volatile("{ .reg .u64 g; cvta.to.global.u64 g, %1; cp.async.cg.shared.global [%0], [g], 16; }"
        :: "r"(dst), "l"(src) : "memory");
}
__device__ __forceinline__ void cp_commit_wait() {
    asm volatile("cp.async.commit_group;" ::: "memory");
    asm volatile("cp.async.wait_group 0;" ::: "memory");
}
__device__ __forceinline__ void ldm_x4(uint32_t* r, uint32_t addr) {
    asm volatile("ldmatrix.sync.aligned.m8n8.x4.shared.b16 {%0,%1,%2,%3}, [%4];"
        : "=r"(r[0]), "=r"(r[1]), "=r"(r[2]), "=r"(r[3]) : "r"(addr));
}
__device__ __forceinline__ void mma_f16(float* d, const uint32_t* a, const uint32_t* b) {
    asm volatile(
        "mma.sync.aligned.m16n8k16.row.col.f32.f16.f16.f32 "
        "{%0,%1,%2,%3}, {%4,%5,%6,%7}, {%8,%9}, {%0,%1,%2,%3};"
        : "+f"(d[0]), "+f"(d[1]), "+f"(d[2]), "+f"(d[3])
        : "r"(a[0]), "r"(a[1]), "r"(a[2]), "r"(a[3]), "r"(b[0]), "r"(b[1]));
}
__device__ __forceinline__ float leaky(float v) { return (v > 0.f) ? v : 0.01f * v; }

// ================= combined weight convert (all 3 MMA layers) =================
__global__ __launch_bounds__(256) void convert_w_all(
    const float* __restrict__ Wm2, const float* __restrict__ bm2,
    const float* __restrict__ Ws2, const float* __restrict__ bs2,
    const float* __restrict__ Wm3, const float* __restrict__ bm3,
    const float* __restrict__ Ws3, const float* __restrict__ bs3,
    const float* __restrict__ Wm4, const float* __restrict__ bm4,
    const float* __restrict__ Ws4, const float* __restrict__ bs4,
    __half* __restrict__ w16, float* __restrict__ bias)
{
    int idx = blockIdx.x * 256 + threadIdx.x;
    int layer, K, COUT;
    const float *Wm, *bm, *Ws, *bs;
    if (idx < 1152 * 128) {
        layer = 0; K = 128; COUT = 128; Wm = Wm2; bm = bm2; Ws = Ws2; bs = bs2;
    } else if (idx < 2 * 1152 * 128) {
        idx -= 1152 * 128;
        layer = 1; K = 128; COUT = 64; Wm = Wm3; bm = bm3; Ws = Ws3; bs = bs3;
    } else if (idx < 2 * 1152 * 128 + 1152 * 64) {
        idx -= 2 * 1152 * 128;
        layer = 2; K = 64; COUT = 64; Wm = Wm4; bm = bm4; Ws = Ws4; bs = bs4;
    } else return;

    const int n = idx / K, k = idx % K;
    float v;
    if (n < 1024)             v = Wm[(size_t)k * 1024 + n];
    else if (n < 1024 + COUT) v = Ws[(size_t)k * COUT + (n - 1024)];
    else                      v = 0.f;
    w16[(size_t)layer * WSLOT + idx] = __float2half(v);
    if (k == 0)
        bias[layer * 1152 + n] = (n < 1024) ? bm[n] : ((n < 1024 + COUT) ? bs[n - 1024] : 0.f);
}

// ================= layer 1: alpha =================
__global__ __launch_bounds__(256) void alpha1(
    const float* __restrict__ x, const float* __restrict__ Wm,
    const float* __restrict__ bm, const float* __restrict__ att)
{
    __shared__ float wm_s[1024], bm_s[1024], att_s[1024];
    const int tid = threadIdx.x;
    for (int i = tid; i < 1024; i += 256) {
        wm_s[i] = Wm[i]; bm_s[i] = bm[i]; att_s[i] = att[i];
    }
    __syncthreads();

    const int w = tid >> 5, l = tid & 31;
    const int g = blockIdx.x * 32 + l;
    const float xv = x[g];
    const int base = w * 128;
    float a = 0.f;
    #pragma unroll 8
    for (int c = 0; c < 128; c++) {
        const float t = leaky(fmaf(xv, wm_s[base + c], bm_s[base + c]));
        a = fmaf(t, att_s[base + c], a);
    }
    g_alpha[(size_t)g * 8 + w] = a;
}

// ================= layer 1: output (agg + self + ELU + split fp16) =================
__global__ __launch_bounds__(256) void out1(
    const float* __restrict__ x,  const float* __restrict__ Wm,
    const float* __restrict__ bm, const float* __restrict__ Ws,
    const float* __restrict__ bs,
    __half* __restrict__ xh, __half* __restrict__ xl)
{
    constexpr int NPB = 32;
    __shared__ float wm_s[1024], bm_s[1024];
    __shared__ float ws_s[128], bs_s[128];
    __shared__ float wgt[NPB][16];
    __shared__ float xs[NPB + 2];

    const int tid = threadIdx.x;
    const int gBase = blockIdx.x * NPB;

    for (int i = tid; i < 1024; i += 256) { wm_s[i] = Wm[i]; bm_s[i] = bm[i]; }
    if (tid < 128) { ws_s[tid] = Ws[tid]; bs_s[tid] = bs[tid]; }
    if (tid < NPB + 2) {
        int gi = gBase + tid - 1;
        gi = (gi < 0) ? 0 : ((gi > NUMNODES - 1) ? NUMNODES - 1 : gi);
        xs[tid] = x[gi];
    }
    {
        const int node = tid >> 3, h = tid & 7;
        const int g = gBase + node;
        const int nch = g & (NCHAIN - 1);
        float el, er;
        if (nch == 0)               { el = 0.f; er = 1.f; }
        else if (nch == NCHAIN - 1) { el = 1.f; er = 0.f; }
        else {
            const float al = g_alpha[(size_t)(g - 1) * 8 + h];
            const float ar = g_alpha[(size_t)(g + 1) * 8 + h];
            const float mx = fmaxf(al, ar);
            el = expf(al - mx); er = expf(ar - mx);
        }
        const float inv = (1.f / ((el + er) + 1e-16f)) * 0.125f;
        wgt[node][h]     = el * inv;
        wgt[node][8 + h] = er * inv;
    }
    __syncthreads();

    const int col = tid & 127;
    float wmv[8], bmv[8];
    #pragma unroll
    for (int h = 0; h < 8; h++) { wmv[h] = wm_s[h * 128 + col]; bmv[h] = bm_s[h * 128 + col]; }
    const float wsc = ws_s[col], bsc = bs_s[col];

    for (int n = (tid >> 7); n < NPB; n += 2) {
        const int g = gBase + n;
        const float xL = xs[n], xS = xs[n + 1], xR = xs[n + 2];
        float s = fmaf(xS, wsc, bsc);
        #pragma unroll
        for (int h = 0; h < 8; h++) {
            const float tL = leaky(fmaf(xL, wmv[h], bmv[h]));
            const float tR = leaky(fmaf(xR, wmv[h], bmv[h]));
            s = fmaf(wgt[n][h], tL, s);
            s = fmaf(wgt[n][8 + h], tR, s);
        }
        s = (s > 0.f) ? s : expm1f(s);           // ELU
        const __half hv = __float2half(s);
        xh[(size_t)g * 128 + col] = hv;
        xl[(size_t)g * 128 + col] = __float2half(s - __half2float(hv));
    }
}

// ================= mma.sync fused GEMM (layers 2-4), 2-pass exact-A =================
// 8 warps (4M x 2N), warp tile 16m x 64n, block tile 64m x 128n.
// B via ldmatrix.x4 consumed immediately (4 regs live).
template<int K, int C>
__global__ __launch_bounds__(256, 3) void gemm_mma(
    const __half* __restrict__ xh, const __half* __restrict__ xl,
    const __half* __restrict__ w16,
    const float* __restrict__ bias, const float* __restrict__ att,
    __half* __restrict__ ymsg, float* __restrict__ yself)
{
    constexpr int SROW = K + 8;
    extern __shared__ __align__(16) char smem[];
    __half* sAh = reinterpret_cast<__half*>(smem);
    __half* sAl = sAh + 64 * SROW;
    __half* sB  = sAl + 64 * SROW;
    float* alpha_s = reinterpret_cast<float*>(sB + 128 * SROW);   // [2][64]

    const int tid  = threadIdx.x;
    const int lane = tid & 31;
    const int wid  = tid >> 5;
    const int warpM = wid & 3;           // 0..3
    const int warpN = wid >> 2;          // 0..1
    const int g = lane >> 2, t = lane & 3;

    const int mBase = blockIdx.x * 64;
    const int nBase = blockIdx.y * 128;
    const bool isMsg = (nBase < 1024);

    // ---- cp.async cooperative loads ----
    {
        constexpr int VPR = K / 8;
        const uint32_t uAh = smem_u32(sAh), uAl = smem_u32(sAl);
        const uint32_t uB = smem_u32(sB);
        const uint4* gAh = reinterpret_cast<const uint4*>(xh + (size_t)mBase * K);
        const uint4* gAl = reinterpret_cast<const uint4*>(xl + (size_t)mBase * K);
        const uint4* gB  = reinterpret_cast<const uint4*>(w16 + (size_t)nBase * K);
        #pragma unroll
        for (int i = 0; i < (64 * VPR) / 256; i++) {
            const int idx = tid + i * 256;
            const int row = idx / VPR, kv = idx % VPR;
            const uint32_t so = (row * (SROW / 8) + kv) * 16;
            cp16(uAh + so, gAh + idx);
            cp16(uAl + so, gAl + idx);
        }
        #pragma unroll
        for (int i = 0; i < (128 * VPR) / 256; i++) {
            const int idx = tid + i * 256;
            const int row = idx / VPR, kv = idx % VPR;
            const uint32_t so = (row * (SROW / 8) + kv) * 16;
            cp16(uB + so, gB + idx);
        }
        cp_commit_wait();
    }
    __syncthreads();

    // ---- MMA mainloop ----
    float acc[8][4];
    #pragma unroll
    for (int ni = 0; ni < 8; ni++)
        #pragma unroll
        for (int e = 0; e < 4; e++) acc[ni][e] = 0.f;

    const uint32_t uAh = smem_u32(sAh), uAl = smem_u32(sAl);
    const uint32_t uB = smem_u32(sB);
    const uint32_t aOfs = ((warpM * 16 + (lane & 15)) * SROW + ((lane >> 4) << 3)) * 2;
    // B x4: lanes 0-7 -> (tile 2p, k+0), 8-15 -> (tile 2p, k+8),
    //       16-23 -> (tile 2p+1, k+0), 24-31 -> (tile 2p+1, k+8)
    const uint32_t bOfs = ((warpN * 64 + ((lane >> 4) << 3) + (lane & 7)) * SROW
                          + (((lane >> 3) & 1) << 3)) * 2;

    #pragma unroll
    for (int kc = 0; kc < K / 16; kc++) {
        const uint32_t kByte = kc * 32;
        uint32_t ah[4], al[4];
        ldm_x4(ah, uAh + aOfs + kByte);
        ldm_x4(al, uAl + aOfs + kByte);
        #pragma unroll
        for (int p = 0; p < 4; p++) {
            uint32_t r[4];
            ldm_x4(r, uB + bOfs + p * (16 * SROW * 2) + kByte);
            mma_f16(acc[2 * p],     ah, r);
            mma_f16(acc[2 * p],     al, r);
            mma_f16(acc[2 * p + 1], ah, r + 2);
            mma_f16(acc[2 * p + 1], al, r + 2);
        }
    }

    // ---- epilogue ----
    float alphaLoc[2] = {0.f, 0.f};
    const int row0 = mBase + warpM * 16 + g;

    #pragma unroll
    for (int ni = 0; ni < 8; ni++) {
        const int n0 = nBase + warpN * 64 + ni * 8 + 2 * t;
        const float2 bb = *reinterpret_cast<const float2*>(&bias[n0]);
        float2 aa = make_float2(0.f, 0.f);
        if (isMsg) aa = *reinterpret_cast<const float2*>(&att[n0]);
        float v0 = acc[ni][0] + bb.x;
        float v1 = acc[ni][1] + bb.y;
        float v2 = acc[ni][2] + bb.x;
        float v3 = acc[ni][3] + bb.y;
        if (isMsg) {
            v0 = leaky(v0); v1 = leaky(v1); v2 = leaky(v2); v3 = leaky(v3);
            alphaLoc[0] = fmaf(v0, aa.x, fmaf(v1, aa.y, alphaLoc[0]));
            alphaLoc[1] = fmaf(v2, aa.x, fmaf(v3, aa.y, alphaLoc[1]));
            *reinterpret_cast<__half2*>(ymsg + (size_t)row0 * 1024 + n0) =
                __floats2half2_rn(v0, v1);
            *reinterpret_cast<__half2*>(ymsg + (size_t)(row0 + 8) * 1024 + n0) =
                __floats2half2_rn(v2, v3);
        } else {
            const int c = n0 - 1024;
            *reinterpret_cast<float2*>(yself + (size_t)row0 * 128 + c) = make_float2(v0, v1);
            *reinterpret_cast<float2*>(yself + (size_t)(row0 + 8) * 128 + c) = make_float2(v2, v3);
        }
    }

    if (isMsg) {
        #pragma unroll
        for (int rh = 0; rh < 2; rh++) {
            float s = alphaLoc[rh];
            s += __shfl_xor_sync(0xffffffffu, s, 1);
            s += __shfl_xor_sync(0xffffffffu, s, 2);
            alphaLoc[rh] = s;
        }
        if (C == 64) {
            // one head per warp's 64-col span
            const int h = blockIdx.y * 2 + warpN;
            if (t == 0) {
                g_alpha[(size_t)row0 * 16 + h]       = alphaLoc[0];
                g_alpha[(size_t)(row0 + 8) * 16 + h] = alphaLoc[1];
            }
        } else {
            // C==128: combine the two N-warps via smem
            if (t == 0) {
                const int lr = warpM * 16 + g;
                alpha_s[warpN * 64 + lr]     = alphaLoc[0];
                alpha_s[warpN * 64 + lr + 8] = alphaLoc[1];
            }
            __syncthreads();
            if (tid < 64)
                g_alpha[(size_t)(mBase + tid) * 8 + blockIdx.y] =
                    alpha_s[tid] + alpha_s[64 + tid];
        }
    }
}

// ================= aggregation stencil (fp16 msg + fp32 self) =================
template<int C, int H, bool ELU, bool SPLIT, bool WF32>
__global__ __launch_bounds__(256) void agg2h(
    const __half* __restrict__ ymsg, const float* __restrict__ yself,
    float* __restrict__ xout,
    __half* __restrict__ xh, __half* __restrict__ xl)
{
    constexpr int TPN = C / 4;
    constexpr int NPB = 256 / TPN;

    __shared__ float wl_s[NPB * H];
    __shared__ float wr_s[NPB * H];

    const int tid = threadIdx.x;
    const int gBase = blockIdx.x * NPB;

    if (tid < NPB * H) {
        const int node = tid / H, h = tid % H;
        const int g = gBase + node;
        const int nch = g & (NCHAIN - 1);
        float el, er;
        if (nch == 0)               { el = 0.f; er = 1.f; }
        else if (nch == NCHAIN - 1) { el = 1.f; er = 0.f; }
        else {
            const float al = g_alpha[(size_t)(g - 1) * H + h];
            const float ar = g_alpha[(size_t)(g + 1) * H + h];
            const float mx = fmaxf(al, ar);
            el = expf(al - mx); er = expf(ar - mx);
        }
        const float inv = (1.f / ((el + er) + 1e-16f)) * (1.f / H);
        wl_s[tid] = el * inv;
        wr_s[tid] = er * inv;
    }
    __syncthreads();

    const int lane = tid % TPN, node = tid / TPN;
    const int g = gBase + node;
    const int nch = g & (NCHAIN - 1);
    const __half* rowL = ymsg + (size_t)((nch > 0)          ? g - 1 : g) * 1024;
    const __half* rowR = ymsg + (size_t)((nch < NCHAIN - 1) ? g + 1 : g) * 1024;
    const int c4 = lane * 4;

    float4 acc = make_float4(0.f, 0.f, 0.f, 0.f);
    #pragma unroll
    for (int h = 0; h < H; h++) {
        const float wl = wl_s[node * H + h];
        const float wr = wr_s[node * H + h];
        const uint2 uL = *reinterpret_cast<const uint2*>(rowL + h * C + c4);
        const uint2 uR = *reinterpret_cast<const uint2*>(rowR + h * C + c4);
        const float2 l0 = __half22float2(*reinterpret_cast<const __half2*>(&uL.x));
        const float2 l1 = __half22float2(*reinterpret_cast<const __half2*>(&uL.y));
        const float2 r0 = __half22float2(*reinterpret_cast<const __half2*>(&uR.x));
        const float2 r1 = __half22float2(*reinterpret_cast<const __half2*>(&uR.y));
        acc.x = fmaf(wl, l0.x, fmaf(wr, r0.x, acc.x));
        acc.y = fmaf(wl, l0.y, fmaf(wr, r0.y, acc.y));
        acc.z = fmaf(wl, l1.x, fmaf(wr, r1.x, acc.z));
        acc.w = fmaf(wl, l1.y, fmaf(wr, r1.y, acc.w));
    }
    const float4 sv = *reinterpret_cast<const float4*>(yself + (size_t)g * 128 + c4);
    acc.x += sv.x; acc.y += sv.y; acc.z += sv.z; acc.w += sv.w;
    if (ELU) {
        acc.x = (acc.x > 0.f) ? acc.x : expm1f(acc.x);
        acc.y = (acc.y > 0.f) ? acc.y : expm1f(acc.y);
        acc.z = (acc.z > 0.f) ? acc.z : expm1f(acc.z);
        acc.w = (acc.w > 0.f) ? acc.w : expm1f(acc.w);
    }
    if (WF32)
        *reinterpret_cast<float4*>(xout + (size_t)g * C + c4) = acc;
    if (SPLIT) {
        const float vv[4] = {acc.x, acc.y, acc.z, acc.w};
        __half hv[4], lv[4];
        #pragma unroll
        for (int e = 0; e < 4; e++) {
            hv[e] = __float2half(vv[e]);
            lv[e] = __float2half(vv[e] - __half2float(hv[e]));
        }
        *reinterpret_cast<uint2*>(xh + (size_t)g * C + c4) = *reinterpret_cast<uint2*>(hv);
        *reinterpret_cast<uint2*>(xl + (size_t)g * C + c4) = *reinterpret_cast<uint2*>(lv);
    }
}

// ================= layer 5 msg+self (fp32, small) =================
__global__ __launch_bounds__(256) void msg5(
    const float* __restrict__ x,  const float* __restrict__ Wm,
    const float* __restrict__ bm, const float* __restrict__ Ws,
    const float* __restrict__ bs, const float* __restrict__ att,
    float* __restrict__ y)
{
    __shared__ float wm_s[64 * 32];
    __shared__ float ws_s[64 * 32];
    __shared__ float x_s[8 * 64];

    const int tid = threadIdx.x;
    const int n = tid >> 5, o = tid & 31;
    const int gBase = blockIdx.x * 8;

    for (int i = tid; i < 64 * 32; i += 256) { wm_s[i] = Wm[i]; ws_s[i] = Ws[i]; }
    for (int i = tid; i < 8 * 64; i += 256)  x_s[i] = x[(size_t)gBase * 64 + i];
    __syncthreads();

    float am = __ldg(&bm[o]);
    float as = __ldg(&bs[o]);
    #pragma unroll
    for (int k = 0; k < 64; k++) {
        const float xv = x_s[n * 64 + k];
        am = fmaf(xv, wm_s[k * 32 + o], am);
        as = fmaf(xv, ws_s[k * 32 + o], as);
    }
    am = leaky(am);
    const int gg = gBase + n;
    y[(size_t)gg * 64 + o]      = am;
    y[(size_t)gg * 64 + 32 + o] = as;

    float a = am * __ldg(&att[o]);
    #pragma unroll
    for (int off = 16; off > 0; off >>= 1)
        a += __shfl_xor_sync(0xffffffffu, a, off);
    if (o == 0) g_alpha[gg] = a;
}

// fp32 agg for layer 5 (C=32, H=1, stride 64)
__global__ __launch_bounds__(256) void agg5(
    const float* __restrict__ y, float* __restrict__ xout)
{
    constexpr int TPN = 8, NPB = 32;
    __shared__ float wl_s[NPB], wr_s[NPB];
    const int tid = threadIdx.x;
    const int gBase = blockIdx.x * NPB;

    if (tid < NPB) {
        const int g = gBase + tid;
        const int nch = g & (NCHAIN - 1);
        float el, er;
        if (nch == 0)               { el = 0.f; er = 1.f; }
        else if (nch == NCHAIN - 1) { el = 1.f; er = 0.f; }
        else {
            const float al = g_alpha[(size_t)(g - 1)];
            const float ar = g_alpha[(size_t)(g + 1)];
            const float mx = fmaxf(al, ar);
            el = expf(al - mx); er = expf(ar - mx);
        }
        const float inv = 1.f / ((el + er) + 1e-16f);
        wl_s[tid] = el * inv;
        wr_s[tid] = er * inv;
    }
    __syncthreads();

    const int lane = tid % TPN, node = tid / TPN;
    const int g = gBase + node;
    const int nch = g & (NCHAIN - 1);
    const float* rowL = y + (size_t)((nch > 0)          ? g - 1 : g) * 64;
    const float* rowR = y + (size_t)((nch < NCHAIN - 1) ? g + 1 : g) * 64;
    const int c4 = lane * 4;
    const float wl = wl_s[node], wr = wr_s[node];
    const float4 mL = *reinterpret_cast<const float4*>(rowL + c4);
    const float4 mR = *reinterpret_cast<const float4*>(rowR + c4);
    const float4 sv = *reinterpret_cast<const float4*>(y + (size_t)g * 64 + 32 + c4);
    float4 acc;
    acc.x = fmaf(wl, mL.x, fmaf(wr, mR.x, sv.x));
    acc.y = fmaf(wl, mL.y, fmaf(wr, mR.y, sv.y));
    acc.z = fmaf(wl, mL.z, fmaf(wr, mR.z, sv.z));
    acc.w = fmaf(wl, mL.w, fmaf(wr, mR.w, sv.w));
    *reinterpret_cast<float4*>(xout + (size_t)g * 32 + c4) = acc;
}

// ================= readout =================
__global__ __launch_bounds__(1024) void final_k(
    const float* __restrict__ x5, const float* __restrict__ Wc,
    const float* __restrict__ bc, float* __restrict__ out, int out_size)
{
    const int tid = threadIdx.x;
    const int b = tid >> 5;
    const int c = tid & 31;
    const float v = x5[((size_t)b * NCHAIN + (NCHAIN - 1)) * 32 + c];
    if (32 + tid < out_size) out[32 + tid] = v;
    float p = v * __ldg(&Wc[c]);
    #pragma unroll
    for (int off = 16; off > 0; off >>= 1)
        p += __shfl_down_sync(0xffffffffu, p, off);
    if (c == 0 && b < out_size) out[b] = p + __ldg(&bc[0]);
}

// ================= launch =================
extern "C" void kernel_launch(void* const* d_in, const int* in_sizes, int n_in,
                              void* d_out, int out_size)
{
    const float* nodes = (const float*)d_in[0];
    const float* Wm1 = (const float*)d_in[1];  const float* bm1 = (const float*)d_in[2];
    const float* Ws1 = (const float*)d_in[3];  const float* bs1 = (const float*)d_in[4];
    const float* att1 = (const float*)d_in[5];
    const float* Wm2 = (const float*)d_in[6];  const float* bm2 = (const float*)d_in[7];
    const float* Ws2 = (const float*)d_in[8];  const float* bs2 = (const float*)d_in[9];
    const float* att2 = (const float*)d_in[10];
    const float* Wm3 = (const float*)d_in[11]; const float* bm3 = (const float*)d_in[12];
    const float* Ws3 = (const float*)d_in[13]; const float* bs3 = (const float*)d_in[14];
    const float* att3 = (const float*)d_in[15];
    const float* Wm4 = (const float*)d_in[16]; const float* bm4 = (const float*)d_in[17];
    const float* Ws4 = (const float*)d_in[18]; const float* bs4 = (const float*)d_in[19];
    const float* att4 = (const float*)d_in[20];
    const float* Wm5 = (const float*)d_in[21]; const float* bm5 = (const float*)d_in[22];
    const float* Ws5 = (const float*)d_in[23]; const float* bs5 = (const float*)d_in[24];
    const float* att5 = (const float*)d_in[25];
    const float* Wc  = (const float*)d_in[26]; const float* bc  = (const float*)d_in[27];

    __half *ymsg, *xh, *xl, *w16;
    float *yself, *bufA, *bufB, *bias;
    cudaGetSymbolAddress((void**)&ymsg,  g_ymsg);
    cudaGetSymbolAddress((void**)&yself, g_yself);
    cudaGetSymbolAddress((void**)&bufA,  g_bufA);
    cudaGetSymbolAddress((void**)&bufB,  g_bufB);
    cudaGetSymbolAddress((void**)&xh,    g_xh);
    cudaGetSymbolAddress((void**)&xl,    g_xl);
    cudaGetSymbolAddress((void**)&w16,   g_w16);
    cudaGetSymbolAddress((void**)&bias,  g_bias);

    const int SM128 = (2 * 64 * 136 + 128 * 136) * 2 + 1024;   // 70,656 B
    const int SM64  = (2 * 64 * 72  + 128 * 72)  * 2 + 1024;   // 37,888 B
    cudaFuncSetAttribute(gemm_mma<128, 128>, cudaFuncAttributeMaxDynamicSharedMemorySize, SM128);
    cudaFuncSetAttribute(gemm_mma<128, 64>,  cudaFuncAttributeMaxDynamicSharedMemorySize, SM128);
    cudaFuncSetAttribute(gemm_mma<64, 64>,   cudaFuncAttributeMaxDynamicSharedMemorySize, SM64);

    const int WTOT = 2 * 1152 * 128 + 1152 * 64;
    convert_w_all<<<(WTOT + 255) / 256, 256>>>(Wm2, bm2, Ws2, bs2,
                                               Wm3, bm3, Ws3, bs3,
                                               Wm4, bm4, Ws4, bs4, w16, bias);

    // Layer 1
    alpha1<<<NUMNODES / 32, 256>>>(nodes, Wm1, bm1, att1);
    out1<<<NUMNODES / 32, 256>>>(nodes, Wm1, bm1, Ws1, bs1, xh, xl);

    const dim3 GG(NUMNODES / 64, 9);

    // Layer 2: K=128, C=128
    gemm_mma<128, 128><<<GG, 256, SM128>>>(xh, xl, w16 + 0 * WSLOT,
                                           bias + 0 * 1152, att2, ymsg, yself);
    agg2h<128, 8, true, true, false><<<NUMNODES / 8, 256>>>(ymsg, yself, nullptr, xh, xl);

    // Layer 3: K=128, C=64
    gemm_mma<128, 64><<<GG, 256, SM128>>>(xh, xl, w16 + 1 * WSLOT,
                                          bias + 1 * 1152, att3, ymsg, yself);
    agg2h<64, 16, true, true, false><<<NUMNODES / 16, 256>>>(ymsg, yself, nullptr, xh, xl);

    // Layer 4: K=64, C=64
    gemm_mma<64, 64><<<GG, 256, SM64>>>(xh, xl, w16 + 2 * WSLOT,
                                        bias + 2 * 1152, att4, ymsg, yself);
    agg2h<64, 16, true, false, true><<<NUMNODES / 16, 256>>>(ymsg, yself, bufB, nullptr, nullptr);

    // Layer 5 (small, fp32) — reuse yself as stride-64 scratch
    msg5<<<NUMNODES / 8, 256>>>(bufB, Wm5, bm5, Ws5, bs5, att5, yself);
    agg5<<<NUMNODES / 32, 256>>>(yself, bufA);

    final_k<<<1, 1024>>>(bufA, Wc, bc, (float*)d_out, out_size);
}

// round 10
// speedup vs baseline: 1.1524x; 1.1524x over previous
#include <cuda_runtime.h>
#include <cuda_fp16.h>
#include <cstdint>
#include <cstddef>

#define NUMNODES 32768
#define NCHAIN   1024

// -------- global scratch (no allocations allowed) --------
__device__ __half g_ymsg[(size_t)NUMNODES * 1024];   // 64 MB msg buffer (fp16)
__device__ float  g_yself[(size_t)NUMNODES * 128];   // 16 MB self buffer (fp32)
__device__ float  g_alpha[(size_t)NUMNODES * 16];
__device__ float  g_bufA[(size_t)NUMNODES * 128];
__device__ float  g_bufB[(size_t)NUMNODES * 128];
__device__ __half g_xq[(size_t)NUMNODES * 128];      // fp16 activations
#define WSLOT (1152 * 128)
__device__ __half g_w16[3 * WSLOT];                  // fp16 weights [n][k]
__device__ float g_bias[3 * 1152];

// ================= PTX helpers (baseline ISA only) =================
__device__ __forceinline__ uint32_t smem_u32(const void* p) {
    uint32_t a;
    asm("{ .reg .u64 t; cvta.to.shared.u64 t, %1; cvt.u32.u64 %0, t; }" : "=r"(a) : "l"(p));
    return a;
}
__device__ __forceinline__ void cp16(uint32_t dst, const void* src) {
    asm volatile("{ .reg .u64 g; cvta.to.global.u64 g, %1; cp.async.cg.shared.global [%0], [g], 16; }"
        :: "r"(dst), "l"(src) : "memory");
}
__device__ __forceinline__ void cp_commit_wait() {
    asm volatile("cp.async.commit_group;" ::: "memory");
    asm volatile("cp.async.wait_group 0;" ::: "memory");
}
__device__ __forceinline__ void ldm_x4(uint32_t* r, uint32_t addr) {
    asm volatile("ldmatrix.sync.aligned.m8n8.x4.shared.b16 {%0,%1,%2,%3}, [%4];"
        : "=r"(r[0]), "=r"(r[1]), "=r"(r[2]), "=r"(r[3]) : "r"(addr));
}
__device__ __forceinline__ void ldm_x2(uint32_t* r, uint32_t addr) {
    asm volatile("ldmatrix.sync.aligned.m8n8.x2.shared.b16 {%0,%1}, [%2];"
        : "=r"(r[0]), "=r"(r[1]) : "r"(addr));
}
__device__ __forceinline__ void mma_f16(float* d, const uint32_t* a, const uint32_t* b) {
    asm volatile(
        "mma.sync.aligned.m16n8k16.row.col.f32.f16.f16.f32 "
        "{%0,%1,%2,%3}, {%4,%5,%6,%7}, {%8,%9}, {%0,%1,%2,%3};"
        : "+f"(d[0]), "+f"(d[1]), "+f"(d[2]), "+f"(d[3])
        : "r"(a[0]), "r"(a[1]), "r"(a[2]), "r"(a[3]), "r"(b[0]), "r"(b[1]));
}
__device__ __forceinline__ float leaky(float v) { return (v > 0.f) ? v : 0.01f * v; }

// ================= combined weight convert (all 3 MMA layers) =================
__global__ __launch_bounds__(256) void convert_w_all(
    const float* __restrict__ Wm2, const float* __restrict__ bm2,
    const float* __restrict__ Ws2, const float* __restrict__ bs2,
    const float* __restrict__ Wm3, const float* __restrict__ bm3,
    const float* __restrict__ Ws3, const float* __restrict__ bs3,
    const float* __restrict__ Wm4, const float* __restrict__ bm4,
    const float* __restrict__ Ws4, const float* __restrict__ bs4,
    __half* __restrict__ w16, float* __restrict__ bias)
{
    int idx = blockIdx.x * 256 + threadIdx.x;
    int layer, K, COUT;
    const float *Wm, *bm, *Ws, *bs;
    if (idx < 1152 * 128) {
        layer = 0; K = 128; COUT = 128; Wm = Wm2; bm = bm2; Ws = Ws2; bs = bs2;
    } else if (idx < 2 * 1152 * 128) {
        idx -= 1152 * 128;
        layer = 1; K = 128; COUT = 64; Wm = Wm3; bm = bm3; Ws = Ws3; bs = bs3;
    } else if (idx < 2 * 1152 * 128 + 1152 * 64) {
        idx -= 2 * 1152 * 128;
        layer = 2; K = 64; COUT = 64; Wm = Wm4; bm = bm4; Ws = Ws4; bs = bs4;
    } else return;

    const int n = idx / K, k = idx % K;
    float v;
    if (n < 1024)             v = Wm[(size_t)k * 1024 + n];
    else if (n < 1024 + COUT) v = Ws[(size_t)k * COUT + (n - 1024)];
    else                      v = 0.f;
    w16[(size_t)layer * WSLOT + idx] = __float2half(v);
    if (k == 0)
        bias[layer * 1152 + n] = (n < 1024) ? bm[n] : ((n < 1024 + COUT) ? bs[n - 1024] : 0.f);
}

// ================= layer 1: alpha =================
__global__ __launch_bounds__(256) void alpha1(
    const float* __restrict__ x, const float* __restrict__ Wm,
    const float* __restrict__ bm, const float* __restrict__ att)
{
    __shared__ float wm_s[1024], bm_s[1024], att_s[1024];
    const int tid = threadIdx.x;
    for (int i = tid; i < 1024; i += 256) {
        wm_s[i] = Wm[i]; bm_s[i] = bm[i]; att_s[i] = att[i];
    }
    __syncthreads();

    const int w = tid >> 5, l = tid & 31;
    const int g = blockIdx.x * 32 + l;
    const float xv = x[g];
    const int base = w * 128;
    float a = 0.f;
    #pragma unroll 8
    for (int c = 0; c < 128; c++) {
        const float t = leaky(fmaf(xv, wm_s[base + c], bm_s[base + c]));
        a = fmaf(t, att_s[base + c], a);
    }
    g_alpha[(size_t)g * 8 + w] = a;
}

// ================= layer 1: output (agg + self + ELU -> fp16) =================
__global__ __launch_bounds__(256) void out1(
    const float* __restrict__ x,  const float* __restrict__ Wm,
    const float* __restrict__ bm, const float* __restrict__ Ws,
    const float* __restrict__ bs,
    __half* __restrict__ xq)
{
    constexpr int NPB = 32;
    __shared__ float wm_s[1024], bm_s[1024];
    __shared__ float ws_s[128], bs_s[128];
    __shared__ float wgt[NPB][16];
    __shared__ float xs[NPB + 2];

    const int tid = threadIdx.x;
    const int gBase = blockIdx.x * NPB;

    for (int i = tid; i < 1024; i += 256) { wm_s[i] = Wm[i]; bm_s[i] = bm[i]; }
    if (tid < 128) { ws_s[tid] = Ws[tid]; bs_s[tid] = bs[tid]; }
    if (tid < NPB + 2) {
        int gi = gBase + tid - 1;
        gi = (gi < 0) ? 0 : ((gi > NUMNODES - 1) ? NUMNODES - 1 : gi);
        xs[tid] = x[gi];
    }
    {
        const int node = tid >> 3, h = tid & 7;
        const int g = gBase + node;
        const int nch = g & (NCHAIN - 1);
        float el, er;
        if (nch == 0)               { el = 0.f; er = 1.f; }
        else if (nch == NCHAIN - 1) { el = 1.f; er = 0.f; }
        else {
            const float al = g_alpha[(size_t)(g - 1) * 8 + h];
            const float ar = g_alpha[(size_t)(g + 1) * 8 + h];
            const float mx = fmaxf(al, ar);
            el = expf(al - mx); er = expf(ar - mx);
        }
        const float inv = (1.f / ((el + er) + 1e-16f)) * 0.125f;
        wgt[node][h]     = el * inv;
        wgt[node][8 + h] = er * inv;
    }
    __syncthreads();

    const int col = tid & 127;
    float wmv[8], bmv[8];
    #pragma unroll
    for (int h = 0; h < 8; h++) { wmv[h] = wm_s[h * 128 + col]; bmv[h] = bm_s[h * 128 + col]; }
    const float wsc = ws_s[col], bsc = bs_s[col];

    for (int n = (tid >> 7); n < NPB; n += 2) {
        const int g = gBase + n;
        const float xL = xs[n], xS = xs[n + 1], xR = xs[n + 2];
        float s = fmaf(xS, wsc, bsc);
        #pragma unroll
        for (int h = 0; h < 8; h++) {
            const float tL = leaky(fmaf(xL, wmv[h], bmv[h]));
            const float tR = leaky(fmaf(xR, wmv[h], bmv[h]));
            s = fmaf(wgt[n][h], tL, s);
            s = fmaf(wgt[n][8 + h], tR, s);
        }
        s = (s > 0.f) ? s : expm1f(s);           // ELU
        xq[(size_t)g * 128 + col] = __float2half(s);
    }
}

// ================= mma.sync fused GEMM (layers 2-4), single fp16 pass =================
// 8 warps (2M x 4N), warp tile 32m x 32n, block tile 64m x 128n (R7 layout).
template<int K, int C>
__global__ __launch_bounds__(256, 3) void gemm_mma(
    const __half* __restrict__ xq, const __half* __restrict__ w16,
    const float* __restrict__ bias, const float* __restrict__ att,
    __half* __restrict__ ymsg, float* __restrict__ yself)
{
    constexpr int SROW = K + 8;
    extern __shared__ __align__(16) char smem[];
    __half* sA = reinterpret_cast<__half*>(smem);
    __half* sB = sA + 64 * SROW;
    float* alpha_s = reinterpret_cast<float*>(sB + 128 * SROW);   // [4][64]

    const int tid  = threadIdx.x;
    const int lane = tid & 31;
    const int wid  = tid >> 5;
    const int warpM = wid >> 2;          // 0..1
    const int warpN = wid & 3;           // 0..3
    const int g = lane >> 2, t = lane & 3;

    const int mBase = blockIdx.x * 64;
    const int nBase = blockIdx.y * 128;
    const bool isMsg = (nBase < 1024);

    // ---- cp.async cooperative loads ----
    {
        constexpr int VPR = K / 8;
        const uint32_t uA = smem_u32(sA);
        const uint32_t uB = smem_u32(sB);
        const uint4* gA = reinterpret_cast<const uint4*>(xq + (size_t)mBase * K);
        const uint4* gB = reinterpret_cast<const uint4*>(w16 + (size_t)nBase * K);
        #pragma unroll
        for (int i = 0; i < (64 * VPR) / 256; i++) {
            const int idx = tid + i * 256;
            const int row = idx / VPR, kv = idx % VPR;
            const uint32_t so = (row * (SROW / 8) + kv) * 16;
            cp16(uA + so, gA + idx);
        }
        #pragma unroll
        for (int i = 0; i < (128 * VPR) / 256; i++) {
            const int idx = tid + i * 256;
            const int row = idx / VPR, kv = idx % VPR;
            const uint32_t so = (row * (SROW / 8) + kv) * 16;
            cp16(uB + so, gB + idx);
        }
        cp_commit_wait();
    }
    __syncthreads();

    // ---- MMA mainloop ----
    float acc[2][4][4];
    #pragma unroll
    for (int mi = 0; mi < 2; mi++)
        #pragma unroll
        for (int ni = 0; ni < 4; ni++)
            #pragma unroll
            for (int e = 0; e < 4; e++) acc[mi][ni][e] = 0.f;

    const uint32_t uA = smem_u32(sA);
    const uint32_t uB = smem_u32(sB);
    const uint32_t aOfs = ((warpM * 32 + (lane & 15)) * SROW + ((lane >> 4) << 3)) * 2;
    const uint32_t bOfs = ((warpN * 32 + (lane & 7)) * SROW + (((lane >> 3) & 1) << 3)) * 2;

    #pragma unroll
    for (int kc = 0; kc < K / 16; kc++) {
        const uint32_t kByte = kc * 32;
        uint32_t a0[4], a1[4];
        ldm_x4(a0, uA + aOfs + kByte);
        ldm_x4(a1, uA + aOfs + (16 * SROW * 2) + kByte);
        #pragma unroll
        for (int ni = 0; ni < 4; ni++) {
            const uint32_t ro = bOfs + ni * (8 * SROW * 2) + kByte;
            uint32_t bw[2];
            ldm_x2(bw, uB + ro);
            mma_f16(acc[0][ni], a0, bw);
            mma_f16(acc[1][ni], a1, bw);
        }
    }

    // ---- epilogue ----
    float alphaLoc[2][2] = {{0.f, 0.f}, {0.f, 0.f}};

    #pragma unroll
    for (int ni = 0; ni < 4; ni++) {
        const int n0 = nBase + warpN * 32 + ni * 8 + 2 * t;
        const float2 bb = *reinterpret_cast<const float2*>(&bias[n0]);
        float2 aa = make_float2(0.f, 0.f);
        if (isMsg) aa = *reinterpret_cast<const float2*>(&att[n0]);
        #pragma unroll
        for (int mi = 0; mi < 2; mi++) {
            float v0 = acc[mi][ni][0] + bb.x;
            float v1 = acc[mi][ni][1] + bb.y;
            float v2 = acc[mi][ni][2] + bb.x;
            float v3 = acc[mi][ni][3] + bb.y;
            const int row0 = mBase + warpM * 32 + mi * 16 + g;
            if (isMsg) {
                v0 = leaky(v0); v1 = leaky(v1); v2 = leaky(v2); v3 = leaky(v3);
                alphaLoc[mi][0] = fmaf(v0, aa.x, fmaf(v1, aa.y, alphaLoc[mi][0]));
                alphaLoc[mi][1] = fmaf(v2, aa.x, fmaf(v3, aa.y, alphaLoc[mi][1]));
                *reinterpret_cast<__half2*>(ymsg + (size_t)row0 * 1024 + n0) =
                    __floats2half2_rn(v0, v1);
                *reinterpret_cast<__half2*>(ymsg + (size_t)(row0 + 8) * 1024 + n0) =
                    __floats2half2_rn(v2, v3);
            } else {
                const int c = n0 - 1024;
                *reinterpret_cast<float2*>(yself + (size_t)row0 * 128 + c) = make_float2(v0, v1);
                *reinterpret_cast<float2*>(yself + (size_t)(row0 + 8) * 128 + c) = make_float2(v2, v3);
            }
        }
    }

    if (isMsg) {
        #pragma unroll
        for (int mi = 0; mi < 2; mi++)
            #pragma unroll
            for (int rh = 0; rh < 2; rh++) {
                float s = alphaLoc[mi][rh];
                s += __shfl_xor_sync(0xffffffffu, s, 1);
                s += __shfl_xor_sync(0xffffffffu, s, 2);
                alphaLoc[mi][rh] = s;
            }
        if (t == 0) {
            #pragma unroll
            for (int mi = 0; mi < 2; mi++) {
                const int lr = warpM * 32 + mi * 16 + g;
                alpha_s[warpN * 64 + lr]     = alphaLoc[mi][0];
                alpha_s[warpN * 64 + lr + 8] = alphaLoc[mi][1];
            }
        }
    }
    __syncthreads();
    if (isMsg) {
        if (C == 128) {
            if (tid < 64) {
                const float s = alpha_s[tid] + alpha_s[64 + tid] +
                                alpha_s[128 + tid] + alpha_s[192 + tid];
                g_alpha[(size_t)(mBase + tid) * 8 + blockIdx.y] = s;
            }
        } else {
            if (tid < 128) {
                const int r = tid & 63, hh = tid >> 6;
                const float s = alpha_s[hh * 128 + r] + alpha_s[hh * 128 + 64 + r];
                g_alpha[(size_t)(mBase + r) * 16 + blockIdx.y * 2 + hh] = s;
            }
        }
    }
}

// ================= aggregation stencil (fp16 msg + fp32 self) =================
template<int C, int H, bool ELU, bool WQ, bool WF32>
__global__ __launch_bounds__(256) void agg2h(
    const __half* __restrict__ ymsg, const float* __restrict__ yself,
    float* __restrict__ xout, __half* __restrict__ xq)
{
    constexpr int TPN = C / 4;
    constexpr int NPB = 256 / TPN;

    __shared__ float wl_s[NPB * H];
    __shared__ float wr_s[NPB * H];

    const int tid = threadIdx.x;
    const int gBase = blockIdx.x * NPB;

    if (tid < NPB * H) {
        const int node = tid / H, h = tid % H;
        const int g = gBase + node;
        const int nch = g & (NCHAIN - 1);
        float el, er;
        if (nch == 0)               { el = 0.f; er = 1.f; }
        else if (nch == NCHAIN - 1) { el = 1.f; er = 0.f; }
        else {
            const float al = g_alpha[(size_t)(g - 1) * H + h];
            const float ar = g_alpha[(size_t)(g + 1) * H + h];
            const float mx = fmaxf(al, ar);
            el = expf(al - mx); er = expf(ar - mx);
        }
        const float inv = (1.f / ((el + er) + 1e-16f)) * (1.f / H);
        wl_s[tid] = el * inv;
        wr_s[tid] = er * inv;
    }
    __syncthreads();

    const int lane = tid % TPN, node = tid / TPN;
    const int g = gBase + node;
    const int nch = g & (NCHAIN - 1);
    const __half* rowL = ymsg + (size_t)((nch > 0)          ? g - 1 : g) * 1024;
    const __half* rowR = ymsg + (size_t)((nch < NCHAIN - 1) ? g + 1 : g) * 1024;
    const int c4 = lane * 4;

    float4 acc = make_float4(0.f, 0.f, 0.f, 0.f);
    #pragma unroll
    for (int h = 0; h < H; h++) {
        const float wl = wl_s[node * H + h];
        const float wr = wr_s[node * H + h];
        const uint2 uL = *reinterpret_cast<const uint2*>(rowL + h * C + c4);
        const uint2 uR = *reinterpret_cast<const uint2*>(rowR + h * C + c4);
        const float2 l0 = __half22float2(*reinterpret_cast<const __half2*>(&uL.x));
        const float2 l1 = __half22float2(*reinterpret_cast<const __half2*>(&uL.y));
        const float2 r0 = __half22float2(*reinterpret_cast<const __half2*>(&uR.x));
        const float2 r1 = __half22float2(*reinterpret_cast<const __half2*>(&uR.y));
        acc.x = fmaf(wl, l0.x, fmaf(wr, r0.x, acc.x));
        acc.y = fmaf(wl, l0.y, fmaf(wr, r0.y, acc.y));
        acc.z = fmaf(wl, l1.x, fmaf(wr, r1.x, acc.z));
        acc.w = fmaf(wl, l1.y, fmaf(wr, r1.y, acc.w));
    }
    const float4 sv = *reinterpret_cast<const float4*>(yself + (size_t)g * 128 + c4);
    acc.x += sv.x; acc.y += sv.y; acc.z += sv.z; acc.w += sv.w;
    if (ELU) {
        acc.x = (acc.x > 0.f) ? acc.x : expm1f(acc.x);
        acc.y = (acc.y > 0.f) ? acc.y : expm1f(acc.y);
        acc.z = (acc.z > 0.f) ? acc.z : expm1f(acc.z);
        acc.w = (acc.w > 0.f) ? acc.w : expm1f(acc.w);
    }
    if (WF32)
        *reinterpret_cast<float4*>(xout + (size_t)g * C + c4) = acc;
    if (WQ) {
        __half hv[4];
        hv[0] = __float2half(acc.x);
        hv[1] = __float2half(acc.y);
        hv[2] = __float2half(acc.z);
        hv[3] = __float2half(acc.w);
        *reinterpret_cast<uint2*>(xq + (size_t)g * C + c4) = *reinterpret_cast<uint2*>(hv);
    }
}

// ================= layer 5 msg+self (fp32, small) =================
__global__ __launch_bounds__(256) void msg5(
    const float* __restrict__ x,  const float* __restrict__ Wm,
    const float* __restrict__ bm, const float* __restrict__ Ws,
    const float* __restrict__ bs, const float* __restrict__ att,
    float* __restrict__ y)
{
    __shared__ float wm_s[64 * 32];
    __shared__ float ws_s[64 * 32];
    __shared__ float x_s[8 * 64];

    const int tid = threadIdx.x;
    const int n = tid >> 5, o = tid & 31;
    const int gBase = blockIdx.x * 8;

    for (int i = tid; i < 64 * 32; i += 256) { wm_s[i] = Wm[i]; ws_s[i] = Ws[i]; }
    for (int i = tid; i < 8 * 64; i += 256)  x_s[i] = x[(size_t)gBase * 64 + i];
    __syncthreads();

    float am = __ldg(&bm[o]);
    float as = __ldg(&bs[o]);
    #pragma unroll
    for (int k = 0; k < 64; k++) {
        const float xv = x_s[n * 64 + k];
        am = fmaf(xv, wm_s[k * 32 + o], am);
        as = fmaf(xv, ws_s[k * 32 + o], as);
    }
    am = leaky(am);
    const int gg = gBase + n;
    y[(size_t)gg * 64 + o]      = am;
    y[(size_t)gg * 64 + 32 + o] = as;

    float a = am * __ldg(&att[o]);
    #pragma unroll
    for (int off = 16; off > 0; off >>= 1)
        a += __shfl_xor_sync(0xffffffffu, a, off);
    if (o == 0) g_alpha[gg] = a;
}

// fp32 agg for layer 5 (C=32, H=1, stride 64)
__global__ __launch_bounds__(256) void agg5(
    const float* __restrict__ y, float* __restrict__ xout)
{
    constexpr int TPN = 8, NPB = 32;
    __shared__ float wl_s[NPB], wr_s[NPB];
    const int tid = threadIdx.x;
    const int gBase = blockIdx.x * NPB;

    if (tid < NPB) {
        const int g = gBase + tid;
        const int nch = g & (NCHAIN - 1);
        float el, er;
        if (nch == 0)               { el = 0.f; er = 1.f; }
        else if (nch == NCHAIN - 1) { el = 1.f; er = 0.f; }
        else {
            const float al = g_alpha[(size_t)(g - 1)];
            const float ar = g_alpha[(size_t)(g + 1)];
            const float mx = fmaxf(al, ar);
            el = expf(al - mx); er = expf(ar - mx);
        }
        const float inv = 1.f / ((el + er) + 1e-16f);
        wl_s[tid] = el * inv;
        wr_s[tid] = er * inv;
    }
    __syncthreads();

    const int lane = tid % TPN, node = tid / TPN;
    const int g = gBase + node;
    const int nch = g & (NCHAIN - 1);
    const float* rowL = y + (size_t)((nch > 0)          ? g - 1 : g) * 64;
    const float* rowR = y + (size_t)((nch < NCHAIN - 1) ? g + 1 : g) * 64;
    const int c4 = lane * 4;
    const float wl = wl_s[node], wr = wr_s[node];
    const float4 mL = *reinterpret_cast<const float4*>(rowL + c4);
    const float4 mR = *reinterpret_cast<const float4*>(rowR + c4);
    const float4 sv = *reinterpret_cast<const float4*>(y + (size_t)g * 64 + 32 + c4);
    float4 acc;
    acc.x = fmaf(wl, mL.x, fmaf(wr, mR.x, sv.x));
    acc.y = fmaf(wl, mL.y, fmaf(wr, mR.y, sv.y));
    acc.z = fmaf(wl, mL.z, fmaf(wr, mR.z, sv.z));
    acc.w = fmaf(wl, mL.w, fmaf(wr, mR.w, sv.w));
    *reinterpret_cast<float4*>(xout + (size_t)g * 32 + c4) = acc;
}

// ================= readout =================
__global__ __launch_bounds__(1024) void final_k(
    const float* __restrict__ x5, const float* __restrict__ Wc,
    const float* __restrict__ bc, float* __restrict__ out, int out_size)
{
    const int tid = threadIdx.x;
    const int b = tid >> 5;
    const int c = tid & 31;
    const float v = x5[((size_t)b * NCHAIN + (NCHAIN - 1)) * 32 + c];
    if (32 + tid < out_size) out[32 + tid] = v;
    float p = v * __ldg(&Wc[c]);
    #pragma unroll
    for (int off = 16; off > 0; off >>= 1)
        p += __shfl_down_sync(0xffffffffu, p, off);
    if (c == 0 && b < out_size) out[b] = p + __ldg(&bc[0]);
}

// ================= launch =================
extern "C" void kernel_launch(void* const* d_in, const int* in_sizes, int n_in,
                              void* d_out, int out_size)
{
    const float* nodes = (const float*)d_in[0];
    const float* Wm1 = (const float*)d_in[1];  const float* bm1 = (const float*)d_in[2];
    const float* Ws1 = (const float*)d_in[3];  const float* bs1 = (const float*)d_in[4];
    const float* att1 = (const float*)d_in[5];
    const float* Wm2 = (const float*)d_in[6];  const float* bm2 = (const float*)d_in[7];
    const float* Ws2 = (const float*)d_in[8];  const float* bs2 = (const float*)d_in[9];
    const float* att2 = (const float*)d_in[10];
    const float* Wm3 = (const float*)d_in[11]; const float* bm3 = (const float*)d_in[12];
    const float* Ws3 = (const float*)d_in[13]; const float* bs3 = (const float*)d_in[14];
    const float* att3 = (const float*)d_in[15];
    const float* Wm4 = (const float*)d_in[16]; const float* bm4 = (const float*)d_in[17];
    const float* Ws4 = (const float*)d_in[18]; const float* bs4 = (const float*)d_in[19];
    const float* att4 = (const float*)d_in[20];
    const float* Wm5 = (const float*)d_in[21]; const float* bm5 = (const float*)d_in[22];
    const float* Ws5 = (const float*)d_in[23]; const float* bs5 = (const float*)d_in[24];
    const float* att5 = (const float*)d_in[25];
    const float* Wc  = (const float*)d_in[26]; const float* bc  = (const float*)d_in[27];

    __half *ymsg, *xq, *w16;
    float *yself, *bufA, *bufB, *bias;
    cudaGetSymbolAddress((void**)&ymsg,  g_ymsg);
    cudaGetSymbolAddress((void**)&yself, g_yself);
    cudaGetSymbolAddress((void**)&bufA,  g_bufA);
    cudaGetSymbolAddress((void**)&bufB,  g_bufB);
    cudaGetSymbolAddress((void**)&xq,    g_xq);
    cudaGetSymbolAddress((void**)&w16,   g_w16);
    cudaGetSymbolAddress((void**)&bias,  g_bias);

    const int SM128 = (64 * 136 + 128 * 136) * 2 + 1024;   // 53,248 B
    const int SM64  = (64 * 72  + 128 * 72)  * 2 + 1024;   // 28,672 B
    cudaFuncSetAttribute(gemm_mma<128, 128>, cudaFuncAttributeMaxDynamicSharedMemorySize, SM128);
    cudaFuncSetAttribute(gemm_mma<128, 64>,  cudaFuncAttributeMaxDynamicSharedMemorySize, SM128);
    cudaFuncSetAttribute(gemm_mma<64, 64>,   cudaFuncAttributeMaxDynamicSharedMemorySize, SM64);

    const int WTOT = 2 * 1152 * 128 + 1152 * 64;
    convert_w_all<<<(WTOT + 255) / 256, 256>>>(Wm2, bm2, Ws2, bs2,
                                               Wm3, bm3, Ws3, bs3,
                                               Wm4, bm4, Ws4, bs4, w16, bias);

    // Layer 1
    alpha1<<<NUMNODES / 32, 256>>>(nodes, Wm1, bm1, att1);
    out1<<<NUMNODES / 32, 256>>>(nodes, Wm1, bm1, Ws1, bs1, xq);

    const dim3 GG(NUMNODES / 64, 9);

    // Layer 2: K=128, C=128
    gemm_mma<128, 128><<<GG, 256, SM128>>>(xq, w16 + 0 * WSLOT,
                                           bias + 0 * 1152, att2, ymsg, yself);
    agg2h<128, 8, true, true, false><<<NUMNODES / 8, 256>>>(ymsg, yself, nullptr, xq);

    // Layer 3: K=128, C=64
    gemm_mma<128, 64><<<GG, 256, SM128>>>(xq, w16 + 1 * WSLOT,
                                          bias + 1 * 1152, att3, ymsg, yself);
    agg2h<64, 16, true, true, false><<<NUMNODES / 16, 256>>>(ymsg, yself, nullptr, xq);

    // Layer 4: K=64, C=64
    gemm_mma<64, 64><<<GG, 256, SM64>>>(xq, w16 + 2 * WSLOT,
                                        bias + 2 * 1152, att4, ymsg, yself);
    agg2h<64, 16, true, false, true><<<NUMNODES / 16, 256>>>(ymsg, yself, bufB, nullptr);

    // Layer 5 (small, fp32) — reuse yself as stride-64 scratch
    msg5<<<NUMNODES / 8, 256>>>(bufB, Wm5, bm5, Ws5, bs5, att5, yself);
    agg5<<<NUMNODES / 32, 256>>>(yself, bufA);

    final_k<<<1, 1024>>>(bufA, Wc, bc, (float*)d_out, out_size);
}

// round 11
// speedup vs baseline: 1.2460x; 1.0812x over previous
#include <cuda_runtime.h>
#include <cuda_fp16.h>
#include <cstdint>
#include <cstddef>

#define NUMNODES 32768
#define NCHAIN   1024

// -------- global scratch (no allocations allowed) --------
__device__ __half g_ymsg[(size_t)NUMNODES * 1024];   // 64 MB msg buffer (fp16)
__device__ float  g_yself[(size_t)NUMNODES * 128];   // 16 MB self buffer (fp32)
__device__ float  g_alpha[(size_t)NUMNODES * 16];
__device__ float  g_bufA[(size_t)NUMNODES * 128];
__device__ float  g_bufB[(size_t)NUMNODES * 128];
__device__ __half g_xq[(size_t)NUMNODES * 128];      // fp16 activations
#define WSLOT (1152 * 128)
__device__ __half g_w16[3 * WSLOT];                  // fp16 weights [n][k]
__device__ float g_bias[3 * 1152];

// ================= PTX helpers (baseline ISA only) =================
__device__ __forceinline__ uint32_t smem_u32(const void* p) {
    uint32_t a;
    asm("{ .reg .u64 t; cvta.to.shared.u64 t, %1; cvt.u32.u64 %0, t; }" : "=r"(a) : "l"(p));
    return a;
}
__device__ __forceinline__ void cp16(uint32_t dst, const void* src) {
    asm volatile("{ .reg .u64 g; cvta.to.global.u64 g, %1; cp.async.cg.shared.global [%0], [g], 16; }"
        :: "r"(dst), "l"(src) : "memory");
}
__device__ __forceinline__ void cp_commit_wait() {
    asm volatile("cp.async.commit_group;" ::: "memory");
    asm volatile("cp.async.wait_group 0;" ::: "memory");
}
__device__ __forceinline__ void ldm_x4(uint32_t* r, uint32_t addr) {
    asm volatile("ldmatrix.sync.aligned.m8n8.x4.shared.b16 {%0,%1,%2,%3}, [%4];"
        : "=r"(r[0]), "=r"(r[1]), "=r"(r[2]), "=r"(r[3]) : "r"(addr));
}
__device__ __forceinline__ void ldm_x2(uint32_t* r, uint32_t addr) {
    asm volatile("ldmatrix.sync.aligned.m8n8.x2.shared.b16 {%0,%1}, [%2];"
        : "=r"(r[0]), "=r"(r[1]) : "r"(addr));
}
__device__ __forceinline__ void mma_f16(float* d, const uint32_t* a, const uint32_t* b) {
    asm volatile(
        "mma.sync.aligned.m16n8k16.row.col.f32.f16.f16.f32 "
        "{%0,%1,%2,%3}, {%4,%5,%6,%7}, {%8,%9}, {%0,%1,%2,%3};"
        : "+f"(d[0]), "+f"(d[1]), "+f"(d[2]), "+f"(d[3])
        : "r"(a[0]), "r"(a[1]), "r"(a[2]), "r"(a[3]), "r"(b[0]), "r"(b[1]));
}
__device__ __forceinline__ float leaky(float v) { return (v > 0.f) ? v : 0.01f * v; }

// ================= combined weight convert (all 3 MMA layers) =================
__global__ __launch_bounds__(256) void convert_w_all(
    const float* __restrict__ Wm2, const float* __restrict__ bm2,
    const float* __restrict__ Ws2, const float* __restrict__ bs2,
    const float* __restrict__ Wm3, const float* __restrict__ bm3,
    const float* __restrict__ Ws3, const float* __restrict__ bs3,
    const float* __restrict__ Wm4, const float* __restrict__ bm4,
    const float* __restrict__ Ws4, const float* __restrict__ bs4,
    __half* __restrict__ w16, float* __restrict__ bias)
{
    int idx = blockIdx.x * 256 + threadIdx.x;
    int layer, K, COUT;
    const float *Wm, *bm, *Ws, *bs;
    if (idx < 1152 * 128) {
        layer = 0; K = 128; COUT = 128; Wm = Wm2; bm = bm2; Ws = Ws2; bs = bs2;
    } else if (idx < 2 * 1152 * 128) {
        idx -= 1152 * 128;
        layer = 1; K = 128; COUT = 64; Wm = Wm3; bm = bm3; Ws = Ws3; bs = bs3;
    } else if (idx < 2 * 1152 * 128 + 1152 * 64) {
        idx -= 2 * 1152 * 128;
        layer = 2; K = 64; COUT = 64; Wm = Wm4; bm = bm4; Ws = Ws4; bs = bs4;
    } else return;

    const int n = idx / K, k = idx % K;
    float v;
    if (n < 1024)             v = Wm[(size_t)k * 1024 + n];
    else if (n < 1024 + COUT) v = Ws[(size_t)k * COUT + (n - 1024)];
    else                      v = 0.f;
    w16[(size_t)layer * WSLOT + idx] = __float2half(v);
    if (k == 0)
        bias[layer * 1152 + n] = (n < 1024) ? bm[n] : ((n < 1024 + COUT) ? bs[n - 1024] : 0.f);
}

// ================= layer 1: alpha =================
__global__ __launch_bounds__(256) void alpha1(
    const float* __restrict__ x, const float* __restrict__ Wm,
    const float* __restrict__ bm, const float* __restrict__ att)
{
    __shared__ float wm_s[1024], bm_s[1024], att_s[1024];
    const int tid = threadIdx.x;
    for (int i = tid; i < 1024; i += 256) {
        wm_s[i] = Wm[i]; bm_s[i] = bm[i]; att_s[i] = att[i];
    }
    __syncthreads();

    const int w = tid >> 5, l = tid & 31;
    const int g = blockIdx.x * 32 + l;
    const float xv = x[g];
    const int base = w * 128;
    float a = 0.f;
    #pragma unroll 8
    for (int c = 0; c < 128; c++) {
        const float t = leaky(fmaf(xv, wm_s[base + c], bm_s[base + c]));
        a = fmaf(t, att_s[base + c], a);
    }
    g_alpha[(size_t)g * 8 + w] = a;
}

// ================= layer 1: output (agg + self + ELU -> fp16) =================
__global__ __launch_bounds__(256) void out1(
    const float* __restrict__ x,  const float* __restrict__ Wm,
    const float* __restrict__ bm, const float* __restrict__ Ws,
    const float* __restrict__ bs,
    __half* __restrict__ xq)
{
    constexpr int NPB = 32;
    __shared__ float wm_s[1024], bm_s[1024];
    __shared__ float ws_s[128], bs_s[128];
    __shared__ float wgt[NPB][16];
    __shared__ float xs[NPB + 2];

    const int tid = threadIdx.x;
    const int gBase = blockIdx.x * NPB;

    for (int i = tid; i < 1024; i += 256) { wm_s[i] = Wm[i]; bm_s[i] = bm[i]; }
    if (tid < 128) { ws_s[tid] = Ws[tid]; bs_s[tid] = bs[tid]; }
    if (tid < NPB + 2) {
        int gi = gBase + tid - 1;
        gi = (gi < 0) ? 0 : ((gi > NUMNODES - 1) ? NUMNODES - 1 : gi);
        xs[tid] = x[gi];
    }
    {
        const int node = tid >> 3, h = tid & 7;
        const int g = gBase + node;
        const int nch = g & (NCHAIN - 1);
        float el, er;
        if (nch == 0)               { el = 0.f; er = 1.f; }
        else if (nch == NCHAIN - 1) { el = 1.f; er = 0.f; }
        else {
            const float al = g_alpha[(size_t)(g - 1) * 8 + h];
            const float ar = g_alpha[(size_t)(g + 1) * 8 + h];
            const float mx = fmaxf(al, ar);
            el = expf(al - mx); er = expf(ar - mx);
        }
        const float inv = (1.f / ((el + er) + 1e-16f)) * 0.125f;
        wgt[node][h]     = el * inv;
        wgt[node][8 + h] = er * inv;
    }
    __syncthreads();

    const int col = tid & 127;
    float wmv[8], bmv[8];
    #pragma unroll
    for (int h = 0; h < 8; h++) { wmv[h] = wm_s[h * 128 + col]; bmv[h] = bm_s[h * 128 + col]; }
    const float wsc = ws_s[col], bsc = bs_s[col];

    for (int n = (tid >> 7); n < NPB; n += 2) {
        const int g = gBase + n;
        const float xL = xs[n], xS = xs[n + 1], xR = xs[n + 2];
        float s = fmaf(xS, wsc, bsc);
        #pragma unroll
        for (int h = 0; h < 8; h++) {
            const float tL = leaky(fmaf(xL, wmv[h], bmv[h]));
            const float tR = leaky(fmaf(xR, wmv[h], bmv[h]));
            s = fmaf(wgt[n][h], tL, s);
            s = fmaf(wgt[n][8 + h], tR, s);
        }
        s = (s > 0.f) ? s : expm1f(s);           // ELU
        xq[(size_t)g * 128 + col] = __float2half(s);
    }
}

// ================= mma.sync fused GEMM (layers 2-4), single fp16 pass =================
// 8 warps (2M x 4N), warp tile 32m x 32n, block tile 64m x 128n.
// Msg tiles: smem-staged fp16 epilogue with fully-coalesced 16B stores.
template<int K, int C>
__global__ __launch_bounds__(256, 3) void gemm_mma(
    const __half* __restrict__ xq, const __half* __restrict__ w16,
    const float* __restrict__ bias, const float* __restrict__ att,
    __half* __restrict__ ymsg, float* __restrict__ yself)
{
    constexpr int SROW = K + 8;
    constexpr int TILEB = (64 * SROW + 128 * SROW) * 2;   // A+B bytes
    constexpr int STRIDE = 136;                           // staging row stride (halfs)
    extern __shared__ __align__(16) char smem[];
    __half* sA = reinterpret_cast<__half*>(smem);
    __half* sB = sA + 64 * SROW;
    __half* sStage = reinterpret_cast<__half*>(smem);     // overlaps tiles (after sync)
    float* alpha_s = reinterpret_cast<float*>(smem + TILEB);   // [4][64]

    const int tid  = threadIdx.x;
    const int lane = tid & 31;
    const int wid  = tid >> 5;
    const int warpM = wid >> 2;          // 0..1
    const int warpN = wid & 3;           // 0..3
    const int g = lane >> 2, t = lane & 3;

    const int mBase = blockIdx.x * 64;
    const int nBase = blockIdx.y * 128;
    const bool isMsg = (nBase < 1024);

    // ---- cp.async cooperative loads ----
    {
        constexpr int VPR = K / 8;
        const uint32_t uA = smem_u32(sA);
        const uint32_t uB = smem_u32(sB);
        const uint4* gA = reinterpret_cast<const uint4*>(xq + (size_t)mBase * K);
        const uint4* gB = reinterpret_cast<const uint4*>(w16 + (size_t)nBase * K);
        #pragma unroll
        for (int i = 0; i < (64 * VPR) / 256; i++) {
            const int idx = tid + i * 256;
            const int row = idx / VPR, kv = idx % VPR;
            const uint32_t so = (row * (SROW / 8) + kv) * 16;
            cp16(uA + so, gA + idx);
        }
        #pragma unroll
        for (int i = 0; i < (128 * VPR) / 256; i++) {
            const int idx = tid + i * 256;
            const int row = idx / VPR, kv = idx % VPR;
            const uint32_t so = (row * (SROW / 8) + kv) * 16;
            cp16(uB + so, gB + idx);
        }
        cp_commit_wait();
    }
    __syncthreads();

    // ---- MMA mainloop ----
    float acc[2][4][4];
    #pragma unroll
    for (int mi = 0; mi < 2; mi++)
        #pragma unroll
        for (int ni = 0; ni < 4; ni++)
            #pragma unroll
            for (int e = 0; e < 4; e++) acc[mi][ni][e] = 0.f;

    const uint32_t uA = smem_u32(sA);
    const uint32_t uB = smem_u32(sB);
    const uint32_t aOfs = ((warpM * 32 + (lane & 15)) * SROW + ((lane >> 4) << 3)) * 2;
    const uint32_t bOfs = ((warpN * 32 + (lane & 7)) * SROW + (((lane >> 3) & 1) << 3)) * 2;

    #pragma unroll
    for (int kc = 0; kc < K / 16; kc++) {
        const uint32_t kByte = kc * 32;
        uint32_t a0[4], a1[4];
        ldm_x4(a0, uA + aOfs + kByte);
        ldm_x4(a1, uA + aOfs + (16 * SROW * 2) + kByte);
        #pragma unroll
        for (int ni = 0; ni < 4; ni++) {
            const uint32_t ro = bOfs + ni * (8 * SROW * 2) + kByte;
            uint32_t bw[2];
            ldm_x2(bw, uB + ro);
            mma_f16(acc[0][ni], a0, bw);
            mma_f16(acc[1][ni], a1, bw);
        }
    }

    __syncthreads();   // protect smem tiles before staging overwrite

    // ---- epilogue ----
    float alphaLoc[2][2] = {{0.f, 0.f}, {0.f, 0.f}};

    #pragma unroll
    for (int ni = 0; ni < 4; ni++) {
        const int n0l = warpN * 32 + ni * 8 + 2 * t;     // local col 0..127
        const int n0 = nBase + n0l;
        const float2 bb = *reinterpret_cast<const float2*>(&bias[n0]);
        float2 aa = make_float2(0.f, 0.f);
        if (isMsg) aa = *reinterpret_cast<const float2*>(&att[n0]);
        #pragma unroll
        for (int mi = 0; mi < 2; mi++) {
            float v0 = acc[mi][ni][0] + bb.x;
            float v1 = acc[mi][ni][1] + bb.y;
            float v2 = acc[mi][ni][2] + bb.x;
            float v3 = acc[mi][ni][3] + bb.y;
            const int r0l = warpM * 32 + mi * 16 + g;    // local row 0..63
            if (isMsg) {
                v0 = leaky(v0); v1 = leaky(v1); v2 = leaky(v2); v3 = leaky(v3);
                alphaLoc[mi][0] = fmaf(v0, aa.x, fmaf(v1, aa.y, alphaLoc[mi][0]));
                alphaLoc[mi][1] = fmaf(v2, aa.x, fmaf(v3, aa.y, alphaLoc[mi][1]));
                *reinterpret_cast<__half2*>(sStage + r0l * STRIDE + n0l) =
                    __floats2half2_rn(v0, v1);
                *reinterpret_cast<__half2*>(sStage + (r0l + 8) * STRIDE + n0l) =
                    __floats2half2_rn(v2, v3);
            } else {
                const int c = n0 - 1024;
                const int row0 = mBase + r0l;
                *reinterpret_cast<float2*>(yself + (size_t)row0 * 128 + c) = make_float2(v0, v1);
                *reinterpret_cast<float2*>(yself + (size_t)(row0 + 8) * 128 + c) = make_float2(v2, v3);
            }
        }
    }

    if (isMsg) {
        #pragma unroll
        for (int mi = 0; mi < 2; mi++)
            #pragma unroll
            for (int rh = 0; rh < 2; rh++) {
                float s = alphaLoc[mi][rh];
                s += __shfl_xor_sync(0xffffffffu, s, 1);
                s += __shfl_xor_sync(0xffffffffu, s, 2);
                alphaLoc[mi][rh] = s;
            }
        if (t == 0) {
            #pragma unroll
            for (int mi = 0; mi < 2; mi++) {
                const int lr = warpM * 32 + mi * 16 + g;
                alpha_s[warpN * 64 + lr]     = alphaLoc[mi][0];
                alpha_s[warpN * 64 + lr + 8] = alphaLoc[mi][1];
            }
        }
        __syncthreads();

        // alpha writes
        if (C == 128) {
            if (tid < 64) {
                const float s = alpha_s[tid] + alpha_s[64 + tid] +
                                alpha_s[128 + tid] + alpha_s[192 + tid];
                g_alpha[(size_t)(mBase + tid) * 8 + blockIdx.y] = s;
            }
        } else {
            if (tid < 128) {
                const int r = tid & 63, hh = tid >> 6;
                const float s = alpha_s[hh * 128 + r] + alpha_s[hh * 128 + 64 + r];
                g_alpha[(size_t)(mBase + r) * 16 + blockIdx.y * 2 + hh] = s;
            }
        }

        // coalesced staging -> global copy: 64 rows x 128 halfs, 16B per thread
        #pragma unroll
        for (int it = 0; it < 4; it++) {
            const int idx = tid + it * 256;
            const int r = idx >> 4;            // 16 uint4 per row
            const int c8 = idx & 15;
            const uint4 v = *reinterpret_cast<const uint4*>(sStage + r * STRIDE + c8 * 8);
            *reinterpret_cast<uint4*>(ymsg + (size_t)(mBase + r) * 1024 + nBase + c8 * 8) = v;
        }
    }
}

// ================= aggregation stencil (fp16 msg + fp32 self) =================
template<int C, int H, bool ELU, bool WQ, bool WF32>
__global__ __launch_bounds__(256) void agg2h(
    const __half* __restrict__ ymsg, const float* __restrict__ yself,
    float* __restrict__ xout, __half* __restrict__ xq)
{
    constexpr int TPN = C / 4;
    constexpr int NPB = 256 / TPN;

    __shared__ float wl_s[NPB * H];
    __shared__ float wr_s[NPB * H];

    const int tid = threadIdx.x;
    const int gBase = blockIdx.x * NPB;

    if (tid < NPB * H) {
        const int node = tid / H, h = tid % H;
        const int g = gBase + node;
        const int nch = g & (NCHAIN - 1);
        float el, er;
        if (nch == 0)               { el = 0.f; er = 1.f; }
        else if (nch == NCHAIN - 1) { el = 1.f; er = 0.f; }
        else {
            const float al = g_alpha[(size_t)(g - 1) * H + h];
            const float ar = g_alpha[(size_t)(g + 1) * H + h];
            const float mx = fmaxf(al, ar);
            el = expf(al - mx); er = expf(ar - mx);
        }
        const float inv = (1.f / ((el + er) + 1e-16f)) * (1.f / H);
        wl_s[tid] = el * inv;
        wr_s[tid] = er * inv;
    }
    __syncthreads();

    const int lane = tid % TPN, node = tid / TPN;
    const int g = gBase + node;
    const int nch = g & (NCHAIN - 1);
    const __half* rowL = ymsg + (size_t)((nch > 0)          ? g - 1 : g) * 1024;
    const __half* rowR = ymsg + (size_t)((nch < NCHAIN - 1) ? g + 1 : g) * 1024;
    const int c4 = lane * 4;

    float4 acc = make_float4(0.f, 0.f, 0.f, 0.f);
    #pragma unroll
    for (int h = 0; h < H; h++) {
        const float wl = wl_s[node * H + h];
        const float wr = wr_s[node * H + h];
        const uint2 uL = *reinterpret_cast<const uint2*>(rowL + h * C + c4);
        const uint2 uR = *reinterpret_cast<const uint2*>(rowR + h * C + c4);
        const float2 l0 = __half22float2(*reinterpret_cast<const __half2*>(&uL.x));
        const float2 l1 = __half22float2(*reinterpret_cast<const __half2*>(&uL.y));
        const float2 r0 = __half22float2(*reinterpret_cast<const __half2*>(&uR.x));
        const float2 r1 = __half22float2(*reinterpret_cast<const __half2*>(&uR.y));
        acc.x = fmaf(wl, l0.x, fmaf(wr, r0.x, acc.x));
        acc.y = fmaf(wl, l0.y, fmaf(wr, r0.y, acc.y));
        acc.z = fmaf(wl, l1.x, fmaf(wr, r1.x, acc.z));
        acc.w = fmaf(wl, l1.y, fmaf(wr, r1.y, acc.w));
    }
    const float4 sv = *reinterpret_cast<const float4*>(yself + (size_t)g * 128 + c4);
    acc.x += sv.x; acc.y += sv.y; acc.z += sv.z; acc.w += sv.w;
    if (ELU) {
        acc.x = (acc.x > 0.f) ? acc.x : expm1f(acc.x);
        acc.y = (acc.y > 0.f) ? acc.y : expm1f(acc.y);
        acc.z = (acc.z > 0.f) ? acc.z : expm1f(acc.z);
        acc.w = (acc.w > 0.f) ? acc.w : expm1f(acc.w);
    }
    if (WF32)
        *reinterpret_cast<float4*>(xout + (size_t)g * C + c4) = acc;
    if (WQ) {
        __half hv[4];
        hv[0] = __float2half(acc.x);
        hv[1] = __float2half(acc.y);
        hv[2] = __float2half(acc.z);
        hv[3] = __float2half(acc.w);
        *reinterpret_cast<uint2*>(xq + (size_t)g * C + c4) = *reinterpret_cast<uint2*>(hv);
    }
}

// ================= layer 5 msg+self (fp32, small) =================
__global__ __launch_bounds__(256) void msg5(
    const float* __restrict__ x,  const float* __restrict__ Wm,
    const float* __restrict__ bm, const float* __restrict__ Ws,
    const float* __restrict__ bs, const float* __restrict__ att,
    float* __restrict__ y)
{
    __shared__ float wm_s[64 * 32];
    __shared__ float ws_s[64 * 32];
    __shared__ float x_s[8 * 64];

    const int tid = threadIdx.x;
    const int n = tid >> 5, o = tid & 31;
    const int gBase = blockIdx.x * 8;

    for (int i = tid; i < 64 * 32; i += 256) { wm_s[i] = Wm[i]; ws_s[i] = Ws[i]; }
    for (int i = tid; i < 8 * 64; i += 256)  x_s[i] = x[(size_t)gBase * 64 + i];
    __syncthreads();

    float am = __ldg(&bm[o]);
    float as = __ldg(&bs[o]);
    #pragma unroll
    for (int k = 0; k < 64; k++) {
        const float xv = x_s[n * 64 + k];
        am = fmaf(xv, wm_s[k * 32 + o], am);
        as = fmaf(xv, ws_s[k * 32 + o], as);
    }
    am = leaky(am);
    const int gg = gBase + n;
    y[(size_t)gg * 64 + o]      = am;
    y[(size_t)gg * 64 + 32 + o] = as;

    float a = am * __ldg(&att[o]);
    #pragma unroll
    for (int off = 16; off > 0; off >>= 1)
        a += __shfl_xor_sync(0xffffffffu, a, off);
    if (o == 0) g_alpha[gg] = a;
}

// fp32 agg for layer 5 (C=32, H=1, stride 64)
__global__ __launch_bounds__(256) void agg5(
    const float* __restrict__ y, float* __restrict__ xout)
{
    constexpr int TPN = 8, NPB = 32;
    __shared__ float wl_s[NPB], wr_s[NPB];
    const int tid = threadIdx.x;
    const int gBase = blockIdx.x * NPB;

    if (tid < NPB) {
        const int g = gBase + tid;
        const int nch = g & (NCHAIN - 1);
        float el, er;
        if (nch == 0)               { el = 0.f; er = 1.f; }
        else if (nch == NCHAIN - 1) { el = 1.f; er = 0.f; }
        else {
            const float al = g_alpha[(size_t)(g - 1)];
            const float ar = g_alpha[(size_t)(g + 1)];
            const float mx = fmaxf(al, ar);
            el = expf(al - mx); er = expf(ar - mx);
        }
        const float inv = 1.f / ((el + er) + 1e-16f);
        wl_s[tid] = el * inv;
        wr_s[tid] = er * inv;
    }
    __syncthreads();

    const int lane = tid % TPN, node = tid / TPN;
    const int g = gBase + node;
    const int nch = g & (NCHAIN - 1);
    const float* rowL = y + (size_t)((nch > 0)          ? g - 1 : g) * 64;
    const float* rowR = y + (size_t)((nch < NCHAIN - 1) ? g + 1 : g) * 64;
    const int c4 = lane * 4;
    const float wl = wl_s[node], wr = wr_s[node];
    const float4 mL = *reinterpret_cast<const float4*>(rowL + c4);
    const float4 mR = *reinterpret_cast<const float4*>(rowR + c4);
    const float4 sv = *reinterpret_cast<const float4*>(y + (size_t)g * 64 + 32 + c4);
    float4 acc;
    acc.x = fmaf(wl, mL.x, fmaf(wr, mR.x, sv.x));
    acc.y = fmaf(wl, mL.y, fmaf(wr, mR.y, sv.y));
    acc.z = fmaf(wl, mL.z, fmaf(wr, mR.z, sv.z));
    acc.w = fmaf(wl, mL.w, fmaf(wr, mR.w, sv.w));
    *reinterpret_cast<float4*>(xout + (size_t)g * 32 + c4) = acc;
}

// ================= readout =================
__global__ __launch_bounds__(1024) void final_k(
    const float* __restrict__ x5, const float* __restrict__ Wc,
    const float* __restrict__ bc, float* __restrict__ out, int out_size)
{
    const int tid = threadIdx.x;
    const int b = tid >> 5;
    const int c = tid & 31;
    const float v = x5[((size_t)b * NCHAIN + (NCHAIN - 1)) * 32 + c];
    if (32 + tid < out_size) out[32 + tid] = v;
    float p = v * __ldg(&Wc[c]);
    #pragma unroll
    for (int off = 16; off > 0; off >>= 1)
        p += __shfl_down_sync(0xffffffffu, p, off);
    if (c == 0 && b < out_size) out[b] = p + __ldg(&bc[0]);
}

// ================= launch =================
extern "C" void kernel_launch(void* const* d_in, const int* in_sizes, int n_in,
                              void* d_out, int out_size)
{
    const float* nodes = (const float*)d_in[0];
    const float* Wm1 = (const float*)d_in[1];  const float* bm1 = (const float*)d_in[2];
    const float* Ws1 = (const float*)d_in[3];  const float* bs1 = (const float*)d_in[4];
    const float* att1 = (const float*)d_in[5];
    const float* Wm2 = (const float*)d_in[6];  const float* bm2 = (const float*)d_in[7];
    const float* Ws2 = (const float*)d_in[8];  const float* bs2 = (const float*)d_in[9];
    const float* att2 = (const float*)d_in[10];
    const float* Wm3 = (const float*)d_in[11]; const float* bm3 = (const float*)d_in[12];
    const float* Ws3 = (const float*)d_in[13]; const float* bs3 = (const float*)d_in[14];
    const float* att3 = (const float*)d_in[15];
    const float* Wm4 = (const float*)d_in[16]; const float* bm4 = (const float*)d_in[17];
    const float* Ws4 = (const float*)d_in[18]; const float* bs4 = (const float*)d_in[19];
    const float* att4 = (const float*)d_in[20];
    const float* Wm5 = (const float*)d_in[21]; const float* bm5 = (const float*)d_in[22];
    const float* Ws5 = (const float*)d_in[23]; const float* bs5 = (const float*)d_in[24];
    const float* att5 = (const float*)d_in[25];
    const float* Wc  = (const float*)d_in[26]; const float* bc  = (const float*)d_in[27];

    __half *ymsg, *xq, *w16;
    float *yself, *bufA, *bufB, *bias;
    cudaGetSymbolAddress((void**)&ymsg,  g_ymsg);
    cudaGetSymbolAddress((void**)&yself, g_yself);
    cudaGetSymbolAddress((void**)&bufA,  g_bufA);
    cudaGetSymbolAddress((void**)&bufB,  g_bufB);
    cudaGetSymbolAddress((void**)&xq,    g_xq);
    cudaGetSymbolAddress((void**)&w16,   g_w16);
    cudaGetSymbolAddress((void**)&bias,  g_bias);

    const int SM128 = (64 * 136 + 128 * 136) * 2 + 1024;   // 53,248 B
    const int SM64  = (64 * 72  + 128 * 72)  * 2 + 1024;   // 28,672 B
    cudaFuncSetAttribute(gemm_mma<128, 128>, cudaFuncAttributeMaxDynamicSharedMemorySize, SM128);
    cudaFuncSetAttribute(gemm_mma<128, 64>,  cudaFuncAttributeMaxDynamicSharedMemorySize, SM128);
    cudaFuncSetAttribute(gemm_mma<64, 64>,   cudaFuncAttributeMaxDynamicSharedMemorySize, SM64);

    const int WTOT = 2 * 1152 * 128 + 1152 * 64;
    convert_w_all<<<(WTOT + 255) / 256, 256>>>(Wm2, bm2, Ws2, bs2,
                                               Wm3, bm3, Ws3, bs3,
                                               Wm4, bm4, Ws4, bs4, w16, bias);

    // Layer 1
    alpha1<<<NUMNODES / 32, 256>>>(nodes, Wm1, bm1, att1);
    out1<<<NUMNODES / 32, 256>>>(nodes, Wm1, bm1, Ws1, bs1, xq);

    const dim3 GG(NUMNODES / 64, 9);

    // Layer 2: K=128, C=128
    gemm_mma<128, 128><<<GG, 256, SM128>>>(xq, w16 + 0 * WSLOT,
                                           bias + 0 * 1152, att2, ymsg, yself);
    agg2h<128, 8, true, true, false><<<NUMNODES / 8, 256>>>(ymsg, yself, nullptr, xq);

    // Layer 3: K=128, C=64
    gemm_mma<128, 64><<<GG, 256, SM128>>>(xq, w16 + 1 * WSLOT,
                                          bias + 1 * 1152, att3, ymsg, yself);
    agg2h<64, 16, true, true, false><<<NUMNODES / 16, 256>>>(ymsg, yself, nullptr, xq);

    // Layer 4: K=64, C=64
    gemm_mma<64, 64><<<GG, 256, SM64>>>(xq, w16 + 2 * WSLOT,
                                        bias + 2 * 1152, att4, ymsg, yself);
    agg2h<64, 16, true, false, true><<<NUMNODES / 16, 256>>>(ymsg, yself, bufB, nullptr);

    // Layer 5 (small, fp32) — reuse yself as stride-64 scratch
    msg5<<<NUMNODES / 8, 256>>>(bufB, Wm5, bm5, Ws5, bs5, att5, yself);
    agg5<<<NUMNODES / 32, 256>>>(yself, bufA);

    final_k<<<1, 1024>>>(bufA, Wc, bc, (float*)d_out, out_size);
}

// round 12
// speedup vs baseline: 1.2736x; 1.0221x over previous
#include <cuda_runtime.h>
#include <cuda_fp16.h>
#include <cstdint>
#include <cstddef>

#define NUMNODES 32768
#define NCHAIN   1024

// -------- global scratch (no allocations allowed) --------
__device__ __half g_ymsg[(size_t)NUMNODES * 1024];   // 64 MB msg buffer (fp16)
__device__ float  g_yself[(size_t)NUMNODES * 128];   // 16 MB self buffer (fp32)
__device__ float  g_alpha[(size_t)NUMNODES * 16];
__device__ float  g_bufA[(size_t)NUMNODES * 128];
__device__ float  g_bufB[(size_t)NUMNODES * 128];
__device__ __half g_xq[(size_t)NUMNODES * 128];      // fp16 activations
#define WSLOT (1152 * 128)
__device__ __half g_w16[3 * WSLOT];                  // fp16 weights [n][k]
__device__ float g_bias[3 * 1152];

// ================= PTX helpers (baseline ISA only) =================
__device__ __forceinline__ uint32_t smem_u32(const void* p) {
    uint32_t a;
    asm("{ .reg .u64 t; cvta.to.shared.u64 t, %1; cvt.u32.u64 %0, t; }" : "=r"(a) : "l"(p));
    return a;
}
__device__ __forceinline__ void cp16(uint32_t dst, const void* src) {
    asm volatile("{ .reg .u64 g; cvta.to.global.u64 g, %1; cp.async.cg.shared.global [%0], [g], 16; }"
        :: "r"(dst), "l"(src) : "memory");
}
__device__ __forceinline__ void cp_commit_wait() {
    asm volatile("cp.async.commit_group;" ::: "memory");
    asm volatile("cp.async.wait_group 0;" ::: "memory");
}
__device__ __forceinline__ void ldm_x4(uint32_t* r, uint32_t addr) {
    asm volatile("ldmatrix.sync.aligned.m8n8.x4.shared.b16 {%0,%1,%2,%3}, [%4];"
        : "=r"(r[0]), "=r"(r[1]), "=r"(r[2]), "=r"(r[3]) : "r"(addr));
}
__device__ __forceinline__ void mma_f16(float* d, const uint32_t* a, const uint32_t* b) {
    asm volatile(
        "mma.sync.aligned.m16n8k16.row.col.f32.f16.f16.f32 "
        "{%0,%1,%2,%3}, {%4,%5,%6,%7}, {%8,%9}, {%0,%1,%2,%3};"
        : "+f"(d[0]), "+f"(d[1]), "+f"(d[2]), "+f"(d[3])
        : "r"(a[0]), "r"(a[1]), "r"(a[2]), "r"(a[3]), "r"(b[0]), "r"(b[1]));
}
__device__ __forceinline__ float leaky(float v) { return (v > 0.f) ? v : 0.01f * v; }

// ================= combined weight convert (all 3 MMA layers) =================
__global__ __launch_bounds__(256) void convert_w_all(
    const float* __restrict__ Wm2, const float* __restrict__ bm2,
    const float* __restrict__ Ws2, const float* __restrict__ bs2,
    const float* __restrict__ Wm3, const float* __restrict__ bm3,
    const float* __restrict__ Ws3, const float* __restrict__ bs3,
    const float* __restrict__ Wm4, const float* __restrict__ bm4,
    const float* __restrict__ Ws4, const float* __restrict__ bs4,
    __half* __restrict__ w16, float* __restrict__ bias)
{
    int idx = blockIdx.x * 256 + threadIdx.x;
    int layer, K, COUT;
    const float *Wm, *bm, *Ws, *bs;
    if (idx < 1152 * 128) {
        layer = 0; K = 128; COUT = 128; Wm = Wm2; bm = bm2; Ws = Ws2; bs = bs2;
    } else if (idx < 2 * 1152 * 128) {
        idx -= 1152 * 128;
        layer = 1; K = 128; COUT = 64; Wm = Wm3; bm = bm3; Ws = Ws3; bs = bs3;
    } else if (idx < 2 * 1152 * 128 + 1152 * 64) {
        idx -= 2 * 1152 * 128;
        layer = 2; K = 64; COUT = 64; Wm = Wm4; bm = bm4; Ws = Ws4; bs = bs4;
    } else return;

    const int n = idx / K, k = idx % K;
    float v;
    if (n < 1024)             v = Wm[(size_t)k * 1024 + n];
    else if (n < 1024 + COUT) v = Ws[(size_t)k * COUT + (n - 1024)];
    else                      v = 0.f;
    w16[(size_t)layer * WSLOT + idx] = __float2half(v);
    if (k == 0)
        bias[layer * 1152 + n] = (n < 1024) ? bm[n] : ((n < 1024 + COUT) ? bs[n - 1024] : 0.f);
}

// ================= layer 1: alpha =================
__global__ __launch_bounds__(256) void alpha1(
    const float* __restrict__ x, const float* __restrict__ Wm,
    const float* __restrict__ bm, const float* __restrict__ att)
{
    __shared__ float wm_s[1024], bm_s[1024], att_s[1024];
    const int tid = threadIdx.x;
    for (int i = tid; i < 1024; i += 256) {
        wm_s[i] = Wm[i]; bm_s[i] = bm[i]; att_s[i] = att[i];
    }
    __syncthreads();

    const int w = tid >> 5, l = tid & 31;
    const int g = blockIdx.x * 32 + l;
    const float xv = x[g];
    const int base = w * 128;
    float a = 0.f;
    #pragma unroll 8
    for (int c = 0; c < 128; c++) {
        const float t = leaky(fmaf(xv, wm_s[base + c], bm_s[base + c]));
        a = fmaf(t, att_s[base + c], a);
    }
    g_alpha[(size_t)g * 8 + w] = a;
}

// ================= layer 1: output (agg + self + ELU -> fp16) =================
__global__ __launch_bounds__(256) void out1(
    const float* __restrict__ x,  const float* __restrict__ Wm,
    const float* __restrict__ bm, const float* __restrict__ Ws,
    const float* __restrict__ bs,
    __half* __restrict__ xq)
{
    constexpr int NPB = 32;
    __shared__ float wm_s[1024], bm_s[1024];
    __shared__ float ws_s[128], bs_s[128];
    __shared__ float wgt[NPB][16];
    __shared__ float xs[NPB + 2];

    const int tid = threadIdx.x;
    const int gBase = blockIdx.x * NPB;

    for (int i = tid; i < 1024; i += 256) { wm_s[i] = Wm[i]; bm_s[i] = bm[i]; }
    if (tid < 128) { ws_s[tid] = Ws[tid]; bs_s[tid] = bs[tid]; }
    if (tid < NPB + 2) {
        int gi = gBase + tid - 1;
        gi = (gi < 0) ? 0 : ((gi > NUMNODES - 1) ? NUMNODES - 1 : gi);
        xs[tid] = x[gi];
    }
    {
        const int node = tid >> 3, h = tid & 7;
        const int g = gBase + node;
        const int nch = g & (NCHAIN - 1);
        float el, er;
        if (nch == 0)               { el = 0.f; er = 1.f; }
        else if (nch == NCHAIN - 1) { el = 1.f; er = 0.f; }
        else {
            const float al = g_alpha[(size_t)(g - 1) * 8 + h];
            const float ar = g_alpha[(size_t)(g + 1) * 8 + h];
            const float mx = fmaxf(al, ar);
            el = expf(al - mx); er = expf(ar - mx);
        }
        const float inv = (1.f / ((el + er) + 1e-16f)) * 0.125f;
        wgt[node][h]     = el * inv;
        wgt[node][8 + h] = er * inv;
    }
    __syncthreads();

    const int col = tid & 127;
    float wmv[8], bmv[8];
    #pragma unroll
    for (int h = 0; h < 8; h++) { wmv[h] = wm_s[h * 128 + col]; bmv[h] = bm_s[h * 128 + col]; }
    const float wsc = ws_s[col], bsc = bs_s[col];

    for (int n = (tid >> 7); n < NPB; n += 2) {
        const int g = gBase + n;
        const float xL = xs[n], xS = xs[n + 1], xR = xs[n + 2];
        float s = fmaf(xS, wsc, bsc);
        #pragma unroll
        for (int h = 0; h < 8; h++) {
            const float tL = leaky(fmaf(xL, wmv[h], bmv[h]));
            const float tR = leaky(fmaf(xR, wmv[h], bmv[h]));
            s = fmaf(wgt[n][h], tL, s);
            s = fmaf(wgt[n][8 + h], tR, s);
        }
        s = (s > 0.f) ? s : expm1f(s);           // ELU
        xq[(size_t)g * 128 + col] = __float2half(s);
    }
}

// ================= mma.sync fused GEMM (layers 2-4) =================
// grid (512, 5): ny<4 -> pair of msg 128-col tiles (A loaded once);
// ny==4 -> self tile. 8 warps (2M x 4N), warp tile 32m x 32n.
// B fragments via ldmatrix.x4; msg epilogue smem-staged, coalesced stores.
template<int K, int C>
__global__ __launch_bounds__(256, 3) void gemm_mma(
    const __half* __restrict__ xq, const __half* __restrict__ w16,
    const float* __restrict__ bias, const float* __restrict__ att,
    __half* __restrict__ ymsg, float* __restrict__ yself)
{
    constexpr int SROW = K + 8;
    constexpr int TILEB = (64 * SROW + 128 * SROW) * 2;   // A+B bytes
    constexpr int STRIDE = 136;                           // staging row stride (halfs)
    extern __shared__ __align__(16) char smem[];
    __half* sA = reinterpret_cast<__half*>(smem);
    __half* sB = sA + 64 * SROW;
    __half* sStage = sB;                                   // staging overlaps B (after sync)
    float* alpha_s = reinterpret_cast<float*>(smem + TILEB);   // [4][64]

    const int tid  = threadIdx.x;
    const int lane = tid & 31;
    const int wid  = tid >> 5;
    const int warpM = wid >> 2;          // 0..1
    const int warpN = wid & 3;           // 0..3
    const int g = lane >> 2, t = lane & 3;

    const int mBase = blockIdx.x * 64;
    const int ny = blockIdx.y;
    const bool isMsg = (ny < 4);
    const int nBase0 = isMsg ? ny * 256 : 1024;

    constexpr int VPR = K / 8;
    const uint32_t uA = smem_u32(sA);
    const uint32_t uB = smem_u32(sB);

    // ---- initial cp.async loads: A tile + first B tile ----
    {
        const uint4* gA = reinterpret_cast<const uint4*>(xq + (size_t)mBase * K);
        const uint4* gB = reinterpret_cast<const uint4*>(w16 + (size_t)nBase0 * K);
        #pragma unroll
        for (int i = 0; i < (64 * VPR) / 256; i++) {
            const int idx = tid + i * 256;
            const int row = idx / VPR, kv = idx % VPR;
            const uint32_t so = (row * (SROW / 8) + kv) * 16;
            cp16(uA + so, gA + idx);
        }
        #pragma unroll
        for (int i = 0; i < (128 * VPR) / 256; i++) {
            const int idx = tid + i * 256;
            const int row = idx / VPR, kv = idx % VPR;
            const uint32_t so = (row * (SROW / 8) + kv) * 16;
            cp16(uB + so, gB + idx);
        }
        cp_commit_wait();
    }

    const uint32_t aOfs = ((warpM * 32 + (lane & 15)) * SROW + ((lane >> 4) << 3)) * 2;
    // B ldmatrix.x4: lanes 0-7 -> rows +0..7 (k+0), 8-15 -> rows +0..7 (k+8),
    //                16-23 -> rows +8..15 (k+0), 24-31 -> rows +8..15 (k+8)
    const uint32_t bOfs = ((warpN * 32 + ((lane >> 4) << 3) + (lane & 7)) * SROW
                          + (((lane >> 3) & 1) << 3)) * 2;

    const int NPASS = isMsg ? 2 : 1;
    for (int p = 0; p < NPASS; p++) {
        const int nBase = nBase0 + p * 128;
        __syncthreads();   // B tile ready / staging copy of prev pass complete

        // ---- MMA mainloop ----
        float acc[2][4][4];
        #pragma unroll
        for (int mi = 0; mi < 2; mi++)
            #pragma unroll
            for (int ni = 0; ni < 4; ni++)
                #pragma unroll
                for (int e = 0; e < 4; e++) acc[mi][ni][e] = 0.f;

        #pragma unroll
        for (int kc = 0; kc < K / 16; kc++) {
            const uint32_t kByte = kc * 32;
            uint32_t a0[4], a1[4], r0[4], r1[4];
            ldm_x4(a0, uA + aOfs + kByte);
            ldm_x4(a1, uA + aOfs + (16 * SROW * 2) + kByte);
            ldm_x4(r0, uB + bOfs + kByte);
            ldm_x4(r1, uB + bOfs + (16 * SROW * 2) + kByte);
            mma_f16(acc[0][0], a0, r0);     mma_f16(acc[1][0], a1, r0);
            mma_f16(acc[0][1], a0, r0 + 2); mma_f16(acc[1][1], a1, r0 + 2);
            mma_f16(acc[0][2], a0, r1);     mma_f16(acc[1][2], a1, r1);
            mma_f16(acc[0][3], a0, r1 + 2); mma_f16(acc[1][3], a1, r1 + 2);
        }

        __syncthreads();   // B reads done before staging overwrite

        // ---- epilogue ----
        if (isMsg) {
            float alphaLoc[2][2] = {{0.f, 0.f}, {0.f, 0.f}};
            #pragma unroll
            for (int ni = 0; ni < 4; ni++) {
                const int n0l = warpN * 32 + ni * 8 + 2 * t;
                const int n0 = nBase + n0l;
                const float2 bb = *reinterpret_cast<const float2*>(&bias[n0]);
                const float2 aa = *reinterpret_cast<const float2*>(&att[n0]);
                #pragma unroll
                for (int mi = 0; mi < 2; mi++) {
                    float v0 = leaky(acc[mi][ni][0] + bb.x);
                    float v1 = leaky(acc[mi][ni][1] + bb.y);
                    float v2 = leaky(acc[mi][ni][2] + bb.x);
                    float v3 = leaky(acc[mi][ni][3] + bb.y);
                    alphaLoc[mi][0] = fmaf(v0, aa.x, fmaf(v1, aa.y, alphaLoc[mi][0]));
                    alphaLoc[mi][1] = fmaf(v2, aa.x, fmaf(v3, aa.y, alphaLoc[mi][1]));
                    const int r0l = warpM * 32 + mi * 16 + g;
                    *reinterpret_cast<__half2*>(sStage + r0l * STRIDE + n0l) =
                        __floats2half2_rn(v0, v1);
                    *reinterpret_cast<__half2*>(sStage + (r0l + 8) * STRIDE + n0l) =
                        __floats2half2_rn(v2, v3);
                }
            }

            #pragma unroll
            for (int mi = 0; mi < 2; mi++)
                #pragma unroll
                for (int rh = 0; rh < 2; rh++) {
                    float s = alphaLoc[mi][rh];
                    s += __shfl_xor_sync(0xffffffffu, s, 1);
                    s += __shfl_xor_sync(0xffffffffu, s, 2);
                    alphaLoc[mi][rh] = s;
                }
            if (t == 0) {
                #pragma unroll
                for (int mi = 0; mi < 2; mi++) {
                    const int lr = warpM * 32 + mi * 16 + g;
                    alpha_s[warpN * 64 + lr]     = alphaLoc[mi][0];
                    alpha_s[warpN * 64 + lr + 8] = alphaLoc[mi][1];
                }
            }
            __syncthreads();

            // alpha writes; tileIdx = ny*2 + p
            const int tileIdx = ny * 2 + p;
            if (C == 128) {
                if (tid < 64) {
                    const float s = alpha_s[tid] + alpha_s[64 + tid] +
                                    alpha_s[128 + tid] + alpha_s[192 + tid];
                    g_alpha[(size_t)(mBase + tid) * 8 + tileIdx] = s;
                }
            } else {
                if (tid < 128) {
                    const int r = tid & 63, hh = tid >> 6;
                    const float s = alpha_s[hh * 128 + r] + alpha_s[hh * 128 + 64 + r];
                    g_alpha[(size_t)(mBase + r) * 16 + tileIdx * 2 + hh] = s;
                }
            }

            // coalesced staging -> global copy: 64 rows x 128 halfs, 16B/thread
            #pragma unroll
            for (int it = 0; it < 4; it++) {
                const int idx = tid + it * 256;
                const int r = idx >> 4;
                const int c8 = idx & 15;
                const uint4 v = *reinterpret_cast<const uint4*>(sStage + r * STRIDE + c8 * 8);
                *reinterpret_cast<uint4*>(ymsg + (size_t)(mBase + r) * 1024 + nBase + c8 * 8) = v;
            }

            // prefetch second B tile (overwrites staging region after copy-out)
            if (p == 0) {
                __syncthreads();
                const uint4* gB = reinterpret_cast<const uint4*>(w16 + (size_t)(nBase0 + 128) * K);
                #pragma unroll
                for (int i = 0; i < (128 * VPR) / 256; i++) {
                    const int idx = tid + i * 256;
                    const int row = idx / VPR, kv = idx % VPR;
                    const uint32_t so = (row * (SROW / 8) + kv) * 16;
                    cp16(uB + so, gB + idx);
                }
                cp_commit_wait();
            }
        } else {
            // self tile: direct fp32 stores
            #pragma unroll
            for (int ni = 0; ni < 4; ni++) {
                const int n0 = nBase + warpN * 32 + ni * 8 + 2 * t;
                const float2 bb = *reinterpret_cast<const float2*>(&bias[n0]);
                const int c = n0 - 1024;
                #pragma unroll
                for (int mi = 0; mi < 2; mi++) {
                    const int row0 = mBase + warpM * 32 + mi * 16 + g;
                    *reinterpret_cast<float2*>(yself + (size_t)row0 * 128 + c) =
                        make_float2(acc[mi][ni][0] + bb.x, acc[mi][ni][1] + bb.y);
                    *reinterpret_cast<float2*>(yself + (size_t)(row0 + 8) * 128 + c) =
                        make_float2(acc[mi][ni][2] + bb.x, acc[mi][ni][3] + bb.y);
                }
            }
        }
    }
}

// ================= aggregation stencil (fp16 msg + fp32 self) =================
template<int C, int H, bool ELU, bool WQ, bool WF32>
__global__ __launch_bounds__(256) void agg2h(
    const __half* __restrict__ ymsg, const float* __restrict__ yself,
    float* __restrict__ xout, __half* __restrict__ xq)
{
    constexpr int TPN = C / 4;
    constexpr int NPB = 256 / TPN;

    __shared__ float wl_s[NPB * H];
    __shared__ float wr_s[NPB * H];

    const int tid = threadIdx.x;
    const int gBase = blockIdx.x * NPB;

    if (tid < NPB * H) {
        const int node = tid / H, h = tid % H;
        const int g = gBase + node;
        const int nch = g & (NCHAIN - 1);
        float el, er;
        if (nch == 0)               { el = 0.f; er = 1.f; }
        else if (nch == NCHAIN - 1) { el = 1.f; er = 0.f; }
        else {
            const float al = g_alpha[(size_t)(g - 1) * H + h];
            const float ar = g_alpha[(size_t)(g + 1) * H + h];
            const float mx = fmaxf(al, ar);
            el = expf(al - mx); er = expf(ar - mx);
        }
        const float inv = (1.f / ((el + er) + 1e-16f)) * (1.f / H);
        wl_s[tid] = el * inv;
        wr_s[tid] = er * inv;
    }
    __syncthreads();

    const int lane = tid % TPN, node = tid / TPN;
    const int g = gBase + node;
    const int nch = g & (NCHAIN - 1);
    const __half* rowL = ymsg + (size_t)((nch > 0)          ? g - 1 : g) * 1024;
    const __half* rowR = ymsg + (size_t)((nch < NCHAIN - 1) ? g + 1 : g) * 1024;
    const int c4 = lane * 4;

    float4 acc = make_float4(0.f, 0.f, 0.f, 0.f);
    #pragma unroll
    for (int h = 0; h < H; h++) {
        const float wl = wl_s[node * H + h];
        const float wr = wr_s[node * H + h];
        const uint2 uL = *reinterpret_cast<const uint2*>(rowL + h * C + c4);
        const uint2 uR = *reinterpret_cast<const uint2*>(rowR + h * C + c4);
        const float2 l0 = __half22float2(*reinterpret_cast<const __half2*>(&uL.x));
        const float2 l1 = __half22float2(*reinterpret_cast<const __half2*>(&uL.y));
        const float2 r0 = __half22float2(*reinterpret_cast<const __half2*>(&uR.x));
        const float2 r1 = __half22float2(*reinterpret_cast<const __half2*>(&uR.y));
        acc.x = fmaf(wl, l0.x, fmaf(wr, r0.x, acc.x));
        acc.y = fmaf(wl, l0.y, fmaf(wr, r0.y, acc.y));
        acc.z = fmaf(wl, l1.x, fmaf(wr, r1.x, acc.z));
        acc.w = fmaf(wl, l1.y, fmaf(wr, r1.y, acc.w));
    }
    const float4 sv = *reinterpret_cast<const float4*>(yself + (size_t)g * 128 + c4);
    acc.x += sv.x; acc.y += sv.y; acc.z += sv.z; acc.w += sv.w;
    if (ELU) {
        acc.x = (acc.x > 0.f) ? acc.x : expm1f(acc.x);
        acc.y = (acc.y > 0.f) ? acc.y : expm1f(acc.y);
        acc.z = (acc.z > 0.f) ? acc.z : expm1f(acc.z);
        acc.w = (acc.w > 0.f) ? acc.w : expm1f(acc.w);
    }
    if (WF32)
        *reinterpret_cast<float4*>(xout + (size_t)g * C + c4) = acc;
    if (WQ) {
        __half hv[4];
        hv[0] = __float2half(acc.x);
        hv[1] = __float2half(acc.y);
        hv[2] = __float2half(acc.z);
        hv[3] = __float2half(acc.w);
        *reinterpret_cast<uint2*>(xq + (size_t)g * C + c4) = *reinterpret_cast<uint2*>(hv);
    }
}

// ================= layer 5 msg+self (fp32, small) =================
__global__ __launch_bounds__(256) void msg5(
    const float* __restrict__ x,  const float* __restrict__ Wm,
    const float* __restrict__ bm, const float* __restrict__ Ws,
    const float* __restrict__ bs, const float* __restrict__ att,
    float* __restrict__ y)
{
    __shared__ float wm_s[64 * 32];
    __shared__ float ws_s[64 * 32];
    __shared__ float x_s[8 * 64];

    const int tid = threadIdx.x;
    const int n = tid >> 5, o = tid & 31;
    const int gBase = blockIdx.x * 8;

    for (int i = tid; i < 64 * 32; i += 256) { wm_s[i] = Wm[i]; ws_s[i] = Ws[i]; }
    for (int i = tid; i < 8 * 64; i += 256)  x_s[i] = x[(size_t)gBase * 64 + i];
    __syncthreads();

    float am = __ldg(&bm[o]);
    float as = __ldg(&bs[o]);
    #pragma unroll
    for (int k = 0; k < 64; k++) {
        const float xv = x_s[n * 64 + k];
        am = fmaf(xv, wm_s[k * 32 + o], am);
        as = fmaf(xv, ws_s[k * 32 + o], as);
    }
    am = leaky(am);
    const int gg = gBase + n;
    y[(size_t)gg * 64 + o]      = am;
    y[(size_t)gg * 64 + 32 + o] = as;

    float a = am * __ldg(&att[o]);
    #pragma unroll
    for (int off = 16; off > 0; off >>= 1)
        a += __shfl_xor_sync(0xffffffffu, a, off);
    if (o == 0) g_alpha[gg] = a;
}

// fp32 agg for layer 5 (C=32, H=1, stride 64)
__global__ __launch_bounds__(256) void agg5(
    const float* __restrict__ y, float* __restrict__ xout)
{
    constexpr int TPN = 8, NPB = 32;
    __shared__ float wl_s[NPB], wr_s[NPB];
    const int tid = threadIdx.x;
    const int gBase = blockIdx.x * NPB;

    if (tid < NPB) {
        const int g = gBase + tid;
        const int nch = g & (NCHAIN - 1);
        float el, er;
        if (nch == 0)               { el = 0.f; er = 1.f; }
        else if (nch == NCHAIN - 1) { el = 1.f; er = 0.f; }
        else {
            const float al = g_alpha[(size_t)(g - 1)];
            const float ar = g_alpha[(size_t)(g + 1)];
            const float mx = fmaxf(al, ar);
            el = expf(al - mx); er = expf(ar - mx);
        }
        const float inv = 1.f / ((el + er) + 1e-16f);
        wl_s[tid] = el * inv;
        wr_s[tid] = er * inv;
    }
    __syncthreads();

    const int lane = tid % TPN, node = tid / TPN;
    const int g = gBase + node;
    const int nch = g & (NCHAIN - 1);
    const float* rowL = y + (size_t)((nch > 0)          ? g - 1 : g) * 64;
    const float* rowR = y + (size_t)((nch < NCHAIN - 1) ? g + 1 : g) * 64;
    const int c4 = lane * 4;
    const float wl = wl_s[node], wr = wr_s[node];
    const float4 mL = *reinterpret_cast<const float4*>(rowL + c4);
    const float4 mR = *reinterpret_cast<const float4*>(rowR + c4);
    const float4 sv = *reinterpret_cast<const float4*>(y + (size_t)g * 64 + 32 + c4);
    float4 acc;
    acc.x = fmaf(wl, mL.x, fmaf(wr, mR.x, sv.x));
    acc.y = fmaf(wl, mL.y, fmaf(wr, mR.y, sv.y));
    acc.z = fmaf(wl, mL.z, fmaf(wr, mR.z, sv.z));
    acc.w = fmaf(wl, mL.w, fmaf(wr, mR.w, sv.w));
    *reinterpret_cast<float4*>(xout + (size_t)g * 32 + c4) = acc;
}

// ================= readout =================
__global__ __launch_bounds__(1024) void final_k(
    const float* __restrict__ x5, const float* __restrict__ Wc,
    const float* __restrict__ bc, float* __restrict__ out, int out_size)
{
    const int tid = threadIdx.x;
    const int b = tid >> 5;
    const int c = tid & 31;
    const float v = x5[((size_t)b * NCHAIN + (NCHAIN - 1)) * 32 + c];
    if (32 + tid < out_size) out[32 + tid] = v;
    float p = v * __ldg(&Wc[c]);
    #pragma unroll
    for (int off = 16; off > 0; off >>= 1)
        p += __shfl_down_sync(0xffffffffu, p, off);
    if (c == 0 && b < out_size) out[b] = p + __ldg(&bc[0]);
}

// ================= launch =================
extern "C" void kernel_launch(void* const* d_in, const int* in_sizes, int n_in,
                              void* d_out, int out_size)
{
    const float* nodes = (const float*)d_in[0];
    const float* Wm1 = (const float*)d_in[1];  const float* bm1 = (const float*)d_in[2];
    const float* Ws1 = (const float*)d_in[3];  const float* bs1 = (const float*)d_in[4];
    const float* att1 = (const float*)d_in[5];
    const float* Wm2 = (const float*)d_in[6];  const float* bm2 = (const float*)d_in[7];
    const float* Ws2 = (const float*)d_in[8];  const float* bs2 = (const float*)d_in[9];
    const float* att2 = (const float*)d_in[10];
    const float* Wm3 = (const float*)d_in[11]; const float* bm3 = (const float*)d_in[12];
    const float* Ws3 = (const float*)d_in[13]; const float* bs3 = (const float*)d_in[14];
    const float* att3 = (const float*)d_in[15];
    const float* Wm4 = (const float*)d_in[16]; const float* bm4 = (const float*)d_in[17];
    const float* Ws4 = (const float*)d_in[18]; const float* bs4 = (const float*)d_in[19];
    const float* att4 = (const float*)d_in[20];
    const float* Wm5 = (const float*)d_in[21]; const float* bm5 = (const float*)d_in[22];
    const float* Ws5 = (const float*)d_in[23]; const float* bs5 = (const float*)d_in[24];
    const float* att5 = (const float*)d_in[25];
    const float* Wc  = (const float*)d_in[26]; const float* bc  = (const float*)d_in[27];

    __half *ymsg, *xq, *w16;
    float *yself, *bufA, *bufB, *bias;
    cudaGetSymbolAddress((void**)&ymsg,  g_ymsg);
    cudaGetSymbolAddress((void**)&yself, g_yself);
    cudaGetSymbolAddress((void**)&bufA,  g_bufA);
    cudaGetSymbolAddress((void**)&bufB,  g_bufB);
    cudaGetSymbolAddress((void**)&xq,    g_xq);
    cudaGetSymbolAddress((void**)&w16,   g_w16);
    cudaGetSymbolAddress((void**)&bias,  g_bias);

    const int SM128 = (64 * 136 + 128 * 136) * 2 + 1024;   // 53,248 B
    const int SM64  = (64 * 72  + 128 * 72)  * 2 + 1024;   // 28,672 B
    cudaFuncSetAttribute(gemm_mma<128, 128>, cudaFuncAttributeMaxDynamicSharedMemorySize, SM128);
    cudaFuncSetAttribute(gemm_mma<128, 64>,  cudaFuncAttributeMaxDynamicSharedMemorySize, SM128);
    cudaFuncSetAttribute(gemm_mma<64, 64>,   cudaFuncAttributeMaxDynamicSharedMemorySize, SM64);

    const int WTOT = 2 * 1152 * 128 + 1152 * 64;
    convert_w_all<<<(WTOT + 255) / 256, 256>>>(Wm2, bm2, Ws2, bs2,
                                               Wm3, bm3, Ws3, bs3,
                                               Wm4, bm4, Ws4, bs4, w16, bias);

    // Layer 1
    alpha1<<<NUMNODES / 32, 256>>>(nodes, Wm1, bm1, att1);
    out1<<<NUMNODES / 32, 256>>>(nodes, Wm1, bm1, Ws1, bs1, xq);

    const dim3 GG(NUMNODES / 64, 5);

    // Layer 2: K=128, C=128
    gemm_mma<128, 128><<<GG, 256, SM128>>>(xq, w16 + 0 * WSLOT,
                                           bias + 0 * 1152, att2, ymsg, yself);
    agg2h<128, 8, true, true, false><<<NUMNODES / 8, 256>>>(ymsg, yself, nullptr, xq);

    // Layer 3: K=128, C=64
    gemm_mma<128, 64><<<GG, 256, SM128>>>(xq, w16 + 1 * WSLOT,
                                          bias + 1 * 1152, att3, ymsg, yself);
    agg2h<64, 16, true, true, false><<<NUMNODES / 16, 256>>>(ymsg, yself, nullptr, xq);

    // Layer 4: K=64, C=64
    gemm_mma<64, 64><<<GG, 256, SM64>>>(xq, w16 + 2 * WSLOT,
                                        bias + 2 * 1152, att4, ymsg, yself);
    agg2h<64, 16, true, false, true><<<NUMNODES / 16, 256>>>(ymsg, yself, bufB, nullptr);

    // Layer 5 (small, fp32) — reuse yself as stride-64 scratch
    msg5<<<NUMNODES / 8, 256>>>(bufB, Wm5, bm5, Ws5, bs5, att5, yself);
    agg5<<<NUMNODES / 32, 256>>>(yself, bufA);

    final_k<<<1, 1024>>>(bufA, Wc, bc, (float*)d_out, out_size);
}

// round 13
// speedup vs baseline: 1.2805x; 1.0055x over previous
#include <cuda_runtime.h>
#include <cuda_fp16.h>
#include <cstdint>
#include <cstddef>

#define NUMNODES 32768
#define NCHAIN   1024

// -------- global scratch (no allocations allowed) --------
__device__ __half g_ymsg[(size_t)NUMNODES * 1024];   // 64 MB msg buffer (fp16)
__device__ float  g_yself[(size_t)NUMNODES * 128];   // 16 MB self buffer (fp32)
__device__ float  g_alpha[(size_t)NUMNODES * 16];
__device__ float  g_bufA[(size_t)NUMNODES * 128];
__device__ float  g_bufB[(size_t)NUMNODES * 128];
__device__ __half g_xq[(size_t)NUMNODES * 128];      // fp16 activations
#define WSLOT (1152 * 128)
__device__ __half g_w16[3 * WSLOT];                  // fp16 weights [n][k]
__device__ float g_bias[3 * 1152];

// ================= PTX helpers (baseline ISA only) =================
__device__ __forceinline__ uint32_t smem_u32(const void* p) {
    uint32_t a;
    asm("{ .reg .u64 t; cvta.to.shared.u64 t, %1; cvt.u32.u64 %0, t; }" : "=r"(a) : "l"(p));
    return a;
}
__device__ __forceinline__ void cp16(uint32_t dst, const void* src) {
    asm volatile("{ .reg .u64 g; cvta.to.global.u64 g, %1; cp.async.cg.shared.global [%0], [g], 16; }"
        :: "r"(dst), "l"(src) : "memory");
}
__device__ __forceinline__ void cp_commit() {
    asm volatile("cp.async.commit_group;" ::: "memory");
}
__device__ __forceinline__ void cp_wait0() {
    asm volatile("cp.async.wait_group 0;" ::: "memory");
}
__device__ __forceinline__ void ldm_x4(uint32_t* r, uint32_t addr) {
    asm volatile("ldmatrix.sync.aligned.m8n8.x4.shared.b16 {%0,%1,%2,%3}, [%4];"
        : "=r"(r[0]), "=r"(r[1]), "=r"(r[2]), "=r"(r[3]) : "r"(addr));
}
__device__ __forceinline__ void mma_f16(float* d, const uint32_t* a, const uint32_t* b) {
    asm volatile(
        "mma.sync.aligned.m16n8k16.row.col.f32.f16.f16.f32 "
        "{%0,%1,%2,%3}, {%4,%5,%6,%7}, {%8,%9}, {%0,%1,%2,%3};"
        : "+f"(d[0]), "+f"(d[1]), "+f"(d[2]), "+f"(d[3])
        : "r"(a[0]), "r"(a[1]), "r"(a[2]), "r"(a[3]), "r"(b[0]), "r"(b[1]));
}
__device__ __forceinline__ float leaky(float v) { return (v > 0.f) ? v : 0.01f * v; }

// ================= combined weight convert (all 3 MMA layers) =================
__global__ __launch_bounds__(256) void convert_w_all(
    const float* __restrict__ Wm2, const float* __restrict__ bm2,
    const float* __restrict__ Ws2, const float* __restrict__ bs2,
    const float* __restrict__ Wm3, const float* __restrict__ bm3,
    const float* __restrict__ Ws3, const float* __restrict__ bs3,
    const float* __restrict__ Wm4, const float* __restrict__ bm4,
    const float* __restrict__ Ws4, const float* __restrict__ bs4,
    __half* __restrict__ w16, float* __restrict__ bias)
{
    int idx = blockIdx.x * 256 + threadIdx.x;
    int layer, K, COUT;
    const float *Wm, *bm, *Ws, *bs;
    if (idx < 1152 * 128) {
        layer = 0; K = 128; COUT = 128; Wm = Wm2; bm = bm2; Ws = Ws2; bs = bs2;
    } else if (idx < 2 * 1152 * 128) {
        idx -= 1152 * 128;
        layer = 1; K = 128; COUT = 64; Wm = Wm3; bm = bm3; Ws = Ws3; bs = bs3;
    } else if (idx < 2 * 1152 * 128 + 1152 * 64) {
        idx -= 2 * 1152 * 128;
        layer = 2; K = 64; COUT = 64; Wm = Wm4; bm = bm4; Ws = Ws4; bs = bs4;
    } else return;

    const int n = idx / K, k = idx % K;
    float v;
    if (n < 1024)             v = Wm[(size_t)k * 1024 + n];
    else if (n < 1024 + COUT) v = Ws[(size_t)k * COUT + (n - 1024)];
    else                      v = 0.f;
    w16[(size_t)layer * WSLOT + idx] = __float2half(v);
    if (k == 0)
        bias[layer * 1152 + n] = (n < 1024) ? bm[n] : ((n < 1024 + COUT) ? bs[n - 1024] : 0.f);
}

// ================= layer 1: alpha =================
__global__ __launch_bounds__(256) void alpha1(
    const float* __restrict__ x, const float* __restrict__ Wm,
    const float* __restrict__ bm, const float* __restrict__ att)
{
    __shared__ float wm_s[1024], bm_s[1024], att_s[1024];
    const int tid = threadIdx.x;
    for (int i = tid; i < 1024; i += 256) {
        wm_s[i] = Wm[i]; bm_s[i] = bm[i]; att_s[i] = att[i];
    }
    __syncthreads();

    const int w = tid >> 5, l = tid & 31;
    const int g = blockIdx.x * 32 + l;
    const float xv = x[g];
    const int base = w * 128;
    float a = 0.f;
    #pragma unroll 8
    for (int c = 0; c < 128; c++) {
        const float t = leaky(fmaf(xv, wm_s[base + c], bm_s[base + c]));
        a = fmaf(t, att_s[base + c], a);
    }
    g_alpha[(size_t)g * 8 + w] = a;
}

// ================= layer 1: output (agg + self + ELU -> fp16) =================
__global__ __launch_bounds__(256) void out1(
    const float* __restrict__ x,  const float* __restrict__ Wm,
    const float* __restrict__ bm, const float* __restrict__ Ws,
    const float* __restrict__ bs,
    __half* __restrict__ xq)
{
    constexpr int NPB = 32;
    __shared__ float wm_s[1024], bm_s[1024];
    __shared__ float ws_s[128], bs_s[128];
    __shared__ float wgt[NPB][16];
    __shared__ float xs[NPB + 2];

    const int tid = threadIdx.x;
    const int gBase = blockIdx.x * NPB;

    for (int i = tid; i < 1024; i += 256) { wm_s[i] = Wm[i]; bm_s[i] = bm[i]; }
    if (tid < 128) { ws_s[tid] = Ws[tid]; bs_s[tid] = bs[tid]; }
    if (tid < NPB + 2) {
        int gi = gBase + tid - 1;
        gi = (gi < 0) ? 0 : ((gi > NUMNODES - 1) ? NUMNODES - 1 : gi);
        xs[tid] = x[gi];
    }
    {
        const int node = tid >> 3, h = tid & 7;
        const int g = gBase + node;
        const int nch = g & (NCHAIN - 1);
        float el, er;
        if (nch == 0)               { el = 0.f; er = 1.f; }
        else if (nch == NCHAIN - 1) { el = 1.f; er = 0.f; }
        else {
            const float al = g_alpha[(size_t)(g - 1) * 8 + h];
            const float ar = g_alpha[(size_t)(g + 1) * 8 + h];
            const float mx = fmaxf(al, ar);
            el = expf(al - mx); er = expf(ar - mx);
        }
        const float inv = (1.f / ((el + er) + 1e-16f)) * 0.125f;
        wgt[node][h]     = el * inv;
        wgt[node][8 + h] = er * inv;
    }
    __syncthreads();

    const int col = tid & 127;
    float wmv[8], bmv[8];
    #pragma unroll
    for (int h = 0; h < 8; h++) { wmv[h] = wm_s[h * 128 + col]; bmv[h] = bm_s[h * 128 + col]; }
    const float wsc = ws_s[col], bsc = bs_s[col];

    for (int n = (tid >> 7); n < NPB; n += 2) {
        const int g = gBase + n;
        const float xL = xs[n], xS = xs[n + 1], xR = xs[n + 2];
        float s = fmaf(xS, wsc, bsc);
        #pragma unroll
        for (int h = 0; h < 8; h++) {
            const float tL = leaky(fmaf(xL, wmv[h], bmv[h]));
            const float tR = leaky(fmaf(xR, wmv[h], bmv[h]));
            s = fmaf(wgt[n][h], tL, s);
            s = fmaf(wgt[n][8 + h], tR, s);
        }
        s = (s > 0.f) ? s : expm1f(s);           // ELU
        xq[(size_t)g * 128 + col] = __float2half(s);
    }
}

// ================= mma.sync fused GEMM (layers 2-4) =================
// grid (512, 5): ny<4 -> pair of msg 128-col tiles (A loaded once);
// ny==4 -> self tile. 8 warps (2M x 4N), warp tile 32m x 32n.
// Dedicated staging buffer: B-tile prefetch for pass 1 overlaps pass-0 epilogue.
template<int K, int C>
__global__ __launch_bounds__(256, 3) void gemm_mma(
    const __half* __restrict__ xq, const __half* __restrict__ w16,
    const float* __restrict__ bias, const float* __restrict__ att,
    __half* __restrict__ ymsg, float* __restrict__ yself)
{
    constexpr int SROW = K + 8;
    constexpr int STRIDE = 136;                           // staging row stride (halfs)
    extern __shared__ __align__(16) char smem[];
    __half* sA = reinterpret_cast<__half*>(smem);
    __half* sB = sA + 64 * SROW;
    __half* sStage = sB + 128 * SROW;                     // dedicated staging
    float* alpha_s = reinterpret_cast<float*>(sStage + 64 * STRIDE);   // [4][64]

    const int tid  = threadIdx.x;
    const int lane = tid & 31;
    const int wid  = tid >> 5;
    const int warpM = wid >> 2;          // 0..1
    const int warpN = wid & 3;           // 0..3
    const int g = lane >> 2, t = lane & 3;

    const int mBase = blockIdx.x * 64;
    const int ny = blockIdx.y;
    const bool isMsg = (ny < 4);
    const int nBase0 = isMsg ? ny * 256 : 1024;

    constexpr int VPR = K / 8;
    const uint32_t uA = smem_u32(sA);
    const uint32_t uB = smem_u32(sB);

    // ---- initial cp.async loads: A tile + first B tile ----
    {
        const uint4* gA = reinterpret_cast<const uint4*>(xq + (size_t)mBase * K);
        const uint4* gB = reinterpret_cast<const uint4*>(w16 + (size_t)nBase0 * K);
        #pragma unroll
        for (int i = 0; i < (64 * VPR) / 256; i++) {
            const int idx = tid + i * 256;
            const int row = idx / VPR, kv = idx % VPR;
            const uint32_t so = (row * (SROW / 8) + kv) * 16;
            cp16(uA + so, gA + idx);
        }
        #pragma unroll
        for (int i = 0; i < (128 * VPR) / 256; i++) {
            const int idx = tid + i * 256;
            const int row = idx / VPR, kv = idx % VPR;
            const uint32_t so = (row * (SROW / 8) + kv) * 16;
            cp16(uB + so, gB + idx);
        }
        cp_commit();
        cp_wait0();
    }
    __syncthreads();

    const uint32_t aOfs = ((warpM * 32 + (lane & 15)) * SROW + ((lane >> 4) << 3)) * 2;
    const uint32_t bOfs = ((warpN * 32 + ((lane >> 4) << 3) + (lane & 7)) * SROW
                          + (((lane >> 3) & 1) << 3)) * 2;

    const int NPASS = isMsg ? 2 : 1;
    for (int p = 0; p < NPASS; p++) {
        const int nBase = nBase0 + p * 128;

        // ---- MMA mainloop ----
        float acc[2][4][4];
        #pragma unroll
        for (int mi = 0; mi < 2; mi++)
            #pragma unroll
            for (int ni = 0; ni < 4; ni++)
                #pragma unroll
                for (int e = 0; e < 4; e++) acc[mi][ni][e] = 0.f;

        #pragma unroll
        for (int kc = 0; kc < K / 16; kc++) {
            const uint32_t kByte = kc * 32;
            uint32_t a0[4], a1[4], r0[4], r1[4];
            ldm_x4(a0, uA + aOfs + kByte);
            ldm_x4(a1, uA + aOfs + (16 * SROW * 2) + kByte);
            ldm_x4(r0, uB + bOfs + kByte);
            ldm_x4(r1, uB + bOfs + (16 * SROW * 2) + kByte);
            mma_f16(acc[0][0], a0, r0);     mma_f16(acc[1][0], a1, r0);
            mma_f16(acc[0][1], a0, r0 + 2); mma_f16(acc[1][1], a1, r0 + 2);
            mma_f16(acc[0][2], a0, r1);     mma_f16(acc[1][2], a1, r1);
            mma_f16(acc[0][3], a0, r1 + 2); mma_f16(acc[1][3], a1, r1 + 2);
        }

        __syncthreads();   // all B-tile reads complete

        if (isMsg) {
            // overlap: kick off B-tile for pass 1 while epilogue runs
            if (p == 0) {
                const uint4* gB = reinterpret_cast<const uint4*>(w16 + (size_t)(nBase0 + 128) * K);
                #pragma unroll
                for (int i = 0; i < (128 * VPR) / 256; i++) {
                    const int idx = tid + i * 256;
                    const int row = idx / VPR, kv = idx % VPR;
                    const uint32_t so = (row * (SROW / 8) + kv) * 16;
                    cp16(uB + so, gB + idx);
                }
                cp_commit();
            }

            // ---- epilogue ----
            float alphaLoc[2][2] = {{0.f, 0.f}, {0.f, 0.f}};
            #pragma unroll
            for (int ni = 0; ni < 4; ni++) {
                const int n0l = warpN * 32 + ni * 8 + 2 * t;
                const int n0 = nBase + n0l;
                const float2 bb = *reinterpret_cast<const float2*>(&bias[n0]);
                const float2 aa = *reinterpret_cast<const float2*>(&att[n0]);
                #pragma unroll
                for (int mi = 0; mi < 2; mi++) {
                    float v0 = leaky(acc[mi][ni][0] + bb.x);
                    float v1 = leaky(acc[mi][ni][1] + bb.y);
                    float v2 = leaky(acc[mi][ni][2] + bb.x);
                    float v3 = leaky(acc[mi][ni][3] + bb.y);
                    alphaLoc[mi][0] = fmaf(v0, aa.x, fmaf(v1, aa.y, alphaLoc[mi][0]));
                    alphaLoc[mi][1] = fmaf(v2, aa.x, fmaf(v3, aa.y, alphaLoc[mi][1]));
                    const int r0l = warpM * 32 + mi * 16 + g;
                    *reinterpret_cast<__half2*>(sStage + r0l * STRIDE + n0l) =
                        __floats2half2_rn(v0, v1);
                    *reinterpret_cast<__half2*>(sStage + (r0l + 8) * STRIDE + n0l) =
                        __floats2half2_rn(v2, v3);
                }
            }

            #pragma unroll
            for (int mi = 0; mi < 2; mi++)
                #pragma unroll
                for (int rh = 0; rh < 2; rh++) {
                    float s = alphaLoc[mi][rh];
                    s += __shfl_xor_sync(0xffffffffu, s, 1);
                    s += __shfl_xor_sync(0xffffffffu, s, 2);
                    alphaLoc[mi][rh] = s;
                }
            if (t == 0) {
                #pragma unroll
                for (int mi = 0; mi < 2; mi++) {
                    const int lr = warpM * 32 + mi * 16 + g;
                    alpha_s[warpN * 64 + lr]     = alphaLoc[mi][0];
                    alpha_s[warpN * 64 + lr + 8] = alphaLoc[mi][1];
                }
            }
            __syncthreads();   // stage + alpha_s writes visible

            const int tileIdx = ny * 2 + p;
            if (C == 128) {
                if (tid < 64) {
                    const float s = alpha_s[tid] + alpha_s[64 + tid] +
                                    alpha_s[128 + tid] + alpha_s[192 + tid];
                    g_alpha[(size_t)(mBase + tid) * 8 + tileIdx] = s;
                }
            } else {
                if (tid < 128) {
                    const int r = tid & 63, hh = tid >> 6;
                    const float s = alpha_s[hh * 128 + r] + alpha_s[hh * 128 + 64 + r];
                    g_alpha[(size_t)(mBase + r) * 16 + tileIdx * 2 + hh] = s;
                }
            }

            // coalesced staging -> global copy: 64 rows x 128 halfs, 16B/thread
            #pragma unroll
            for (int it = 0; it < 4; it++) {
                const int idx = tid + it * 256;
                const int r = idx >> 4;
                const int c8 = idx & 15;
                const uint4 v = *reinterpret_cast<const uint4*>(sStage + r * STRIDE + c8 * 8);
                *reinterpret_cast<uint4*>(ymsg + (size_t)(mBase + r) * 1024 + nBase + c8 * 8) = v;
            }

            if (p == 0) {
                cp_wait0();        // B1 landed (mostly overlapped by epilogue)
                __syncthreads();
            }
        } else {
            // self tile: direct fp32 stores
            #pragma unroll
            for (int ni = 0; ni < 4; ni++) {
                const int n0 = nBase + warpN * 32 + ni * 8 + 2 * t;
                const float2 bb = *reinterpret_cast<const float2*>(&bias[n0]);
                const int c = n0 - 1024;
                #pragma unroll
                for (int mi = 0; mi < 2; mi++) {
                    const int row0 = mBase + warpM * 32 + mi * 16 + g;
                    *reinterpret_cast<float2*>(yself + (size_t)row0 * 128 + c) =
                        make_float2(acc[mi][ni][0] + bb.x, acc[mi][ni][1] + bb.y);
                    *reinterpret_cast<float2*>(yself + (size_t)(row0 + 8) * 128 + c) =
                        make_float2(acc[mi][ni][2] + bb.x, acc[mi][ni][3] + bb.y);
                }
            }
        }
    }
}

// ================= aggregation stencil (fp16 msg + fp32 self) =================
template<int C, int H, bool ELU, bool WQ, bool WF32>
__global__ __launch_bounds__(256) void agg2h(
    const __half* __restrict__ ymsg, const float* __restrict__ yself,
    float* __restrict__ xout, __half* __restrict__ xq)
{
    constexpr int TPN = C / 4;
    constexpr int NPB = 256 / TPN;

    __shared__ float wl_s[NPB * H];
    __shared__ float wr_s[NPB * H];

    const int tid = threadIdx.x;
    const int gBase = blockIdx.x * NPB;

    if (tid < NPB * H) {
        const int node = tid / H, h = tid % H;
        const int g = gBase + node;
        const int nch = g & (NCHAIN - 1);
        float el, er;
        if (nch == 0)               { el = 0.f; er = 1.f; }
        else if (nch == NCHAIN - 1) { el = 1.f; er = 0.f; }
        else {
            const float al = g_alpha[(size_t)(g - 1) * H + h];
            const float ar = g_alpha[(size_t)(g + 1) * H + h];
            const float mx = fmaxf(al, ar);
            el = expf(al - mx); er = expf(ar - mx);
        }
        const float inv = (1.f / ((el + er) + 1e-16f)) * (1.f / H);
        wl_s[tid] = el * inv;
        wr_s[tid] = er * inv;
    }
    __syncthreads();

    const int lane = tid % TPN, node = tid / TPN;
    const int g = gBase + node;
    const int nch = g & (NCHAIN - 1);
    const __half* rowL = ymsg + (size_t)((nch > 0)          ? g - 1 : g) * 1024;
    const __half* rowR = ymsg + (size_t)((nch < NCHAIN - 1) ? g + 1 : g) * 1024;
    const int c4 = lane * 4;

    float4 acc = make_float4(0.f, 0.f, 0.f, 0.f);
    #pragma unroll
    for (int h = 0; h < H; h++) {
        const float wl = wl_s[node * H + h];
        const float wr = wr_s[node * H + h];
        const uint2 uL = *reinterpret_cast<const uint2*>(rowL + h * C + c4);
        const uint2 uR = *reinterpret_cast<const uint2*>(rowR + h * C + c4);
        const float2 l0 = __half22float2(*reinterpret_cast<const __half2*>(&uL.x));
        const float2 l1 = __half22float2(*reinterpret_cast<const __half2*>(&uL.y));
        const float2 r0 = __half22float2(*reinterpret_cast<const __half2*>(&uR.x));
        const float2 r1 = __half22float2(*reinterpret_cast<const __half2*>(&uR.y));
        acc.x = fmaf(wl, l0.x, fmaf(wr, r0.x, acc.x));
        acc.y = fmaf(wl, l0.y, fmaf(wr, r0.y, acc.y));
        acc.z = fmaf(wl, l1.x, fmaf(wr, r1.x, acc.z));
        acc.w = fmaf(wl, l1.y, fmaf(wr, r1.y, acc.w));
    }
    const float4 sv = *reinterpret_cast<const float4*>(yself + (size_t)g * 128 + c4);
    acc.x += sv.x; acc.y += sv.y; acc.z += sv.z; acc.w += sv.w;
    if (ELU) {
        acc.x = (acc.x > 0.f) ? acc.x : expm1f(acc.x);
        acc.y = (acc.y > 0.f) ? acc.y : expm1f(acc.y);
        acc.z = (acc.z > 0.f) ? acc.z : expm1f(acc.z);
        acc.w = (acc.w > 0.f) ? acc.w : expm1f(acc.w);
    }
    if (WF32)
        *reinterpret_cast<float4*>(xout + (size_t)g * C + c4) = acc;
    if (WQ) {
        __half hv[4];
        hv[0] = __float2half(acc.x);
        hv[1] = __float2half(acc.y);
        hv[2] = __float2half(acc.z);
        hv[3] = __float2half(acc.w);
        *reinterpret_cast<uint2*>(xq + (size_t)g * C + c4) = *reinterpret_cast<uint2*>(hv);
    }
}

// ================= layer 5 msg+self (fp32, small) =================
__global__ __launch_bounds__(256) void msg5(
    const float* __restrict__ x,  const float* __restrict__ Wm,
    const float* __restrict__ bm, const float* __restrict__ Ws,
    const float* __restrict__ bs, const float* __restrict__ att,
    float* __restrict__ y)
{
    __shared__ float wm_s[64 * 32];
    __shared__ float ws_s[64 * 32];
    __shared__ float x_s[8 * 64];

    const int tid = threadIdx.x;
    const int n = tid >> 5, o = tid & 31;
    const int gBase = blockIdx.x * 8;

    for (int i = tid; i < 64 * 32; i += 256) { wm_s[i] = Wm[i]; ws_s[i] = Ws[i]; }
    for (int i = tid; i < 8 * 64; i += 256)  x_s[i] = x[(size_t)gBase * 64 + i];
    __syncthreads();

    float am = __ldg(&bm[o]);
    float as = __ldg(&bs[o]);
    #pragma unroll
    for (int k = 0; k < 64; k++) {
        const float xv = x_s[n * 64 + k];
        am = fmaf(xv, wm_s[k * 32 + o], am);
        as = fmaf(xv, ws_s[k * 32 + o], as);
    }
    am = leaky(am);
    const int gg = gBase + n;
    y[(size_t)gg * 64 + o]      = am;
    y[(size_t)gg * 64 + 32 + o] = as;

    float a = am * __ldg(&att[o]);
    #pragma unroll
    for (int off = 16; off > 0; off >>= 1)
        a += __shfl_xor_sync(0xffffffffu, a, off);
    if (o == 0) g_alpha[gg] = a;
}

// fp32 agg for layer 5 (C=32, H=1, stride 64)
__global__ __launch_bounds__(256) void agg5(
    const float* __restrict__ y, float* __restrict__ xout)
{
    constexpr int TPN = 8, NPB = 32;
    __shared__ float wl_s[NPB], wr_s[NPB];
    const int tid = threadIdx.x;
    const int gBase = blockIdx.x * NPB;

    if (tid < NPB) {
        const int g = gBase + tid;
        const int nch = g & (NCHAIN - 1);
        float el, er;
        if (nch == 0)               { el = 0.f; er = 1.f; }
        else if (nch == NCHAIN - 1) { el = 1.f; er = 0.f; }
        else {
            const float al = g_alpha[(size_t)(g - 1)];
            const float ar = g_alpha[(size_t)(g + 1)];
            const float mx = fmaxf(al, ar);
            el = expf(al - mx); er = expf(ar - mx);
        }
        const float inv = 1.f / ((el + er) + 1e-16f);
        wl_s[tid] = el * inv;
        wr_s[tid] = er * inv;
    }
    __syncthreads();

    const int lane = tid % TPN, node = tid / TPN;
    const int g = gBase + node;
    const int nch = g & (NCHAIN - 1);
    const float* rowL = y + (size_t)((nch > 0)          ? g - 1 : g) * 64;
    const float* rowR = y + (size_t)((nch < NCHAIN - 1) ? g + 1 : g) * 64;
    const int c4 = lane * 4;
    const float wl = wl_s[node], wr = wr_s[node];
    const float4 mL = *reinterpret_cast<const float4*>(rowL + c4);
    const float4 mR = *reinterpret_cast<const float4*>(rowR + c4);
    const float4 sv = *reinterpret_cast<const float4*>(y + (size_t)g * 64 + 32 + c4);
    float4 acc;
    acc.x = fmaf(wl, mL.x, fmaf(wr, mR.x, sv.x));
    acc.y = fmaf(wl, mL.y, fmaf(wr, mR.y, sv.y));
    acc.z = fmaf(wl, mL.z, fmaf(wr, mR.z, sv.z));
    acc.w = fmaf(wl, mL.w, fmaf(wr, mR.w, sv.w));
    *reinterpret_cast<float4*>(xout + (size_t)g * 32 + c4) = acc;
}

// ================= readout =================
__global__ __launch_bounds__(1024) void final_k(
    const float* __restrict__ x5, const float* __restrict__ Wc,
    const float* __restrict__ bc, float* __restrict__ out, int out_size)
{
    const int tid = threadIdx.x;
    const int b = tid >> 5;
    const int c = tid & 31;
    const float v = x5[((size_t)b * NCHAIN + (NCHAIN - 1)) * 32 + c];
    if (32 + tid < out_size) out[32 + tid] = v;
    float p = v * __ldg(&Wc[c]);
    #pragma unroll
    for (int off = 16; off > 0; off >>= 1)
        p += __shfl_down_sync(0xffffffffu, p, off);
    if (c == 0 && b < out_size) out[b] = p + __ldg(&bc[0]);
}

// ================= launch =================
extern "C" void kernel_launch(void* const* d_in, const int* in_sizes, int n_in,
                              void* d_out, int out_size)
{
    const float* nodes = (const float*)d_in[0];
    const float* Wm1 = (const float*)d_in[1];  const float* bm1 = (const float*)d_in[2];
    const float* Ws1 = (const float*)d_in[3];  const float* bs1 = (const float*)d_in[4];
    const float* att1 = (const float*)d_in[5];
    const float* Wm2 = (const float*)d_in[6];  const float* bm2 = (const float*)d_in[7];
    const float* Ws2 = (const float*)d_in[8];  const float* bs2 = (const float*)d_in[9];
    const float* att2 = (const float*)d_in[10];
    const float* Wm3 = (const float*)d_in[11]; const float* bm3 = (const float*)d_in[12];
    const float* Ws3 = (const float*)d_in[13]; const float* bs3 = (const float*)d_in[14];
    const float* att3 = (const float*)d_in[15];
    const float* Wm4 = (const float*)d_in[16]; const float* bm4 = (const float*)d_in[17];
    const float* Ws4 = (const float*)d_in[18]; const float* bs4 = (const float*)d_in[19];
    const float* att4 = (const float*)d_in[20];
    const float* Wm5 = (const float*)d_in[21]; const float* bm5 = (const float*)d_in[22];
    const float* Ws5 = (const float*)d_in[23]; const float* bs5 = (const float*)d_in[24];
    const float* att5 = (const float*)d_in[25];
    const float* Wc  = (const float*)d_in[26]; const float* bc  = (const float*)d_in[27];

    __half *ymsg, *xq, *w16;
    float *yself, *bufA, *bufB, *bias;
    cudaGetSymbolAddress((void**)&ymsg,  g_ymsg);
    cudaGetSymbolAddress((void**)&yself, g_yself);
    cudaGetSymbolAddress((void**)&bufA,  g_bufA);
    cudaGetSymbolAddress((void**)&bufB,  g_bufB);
    cudaGetSymbolAddress((void**)&xq,    g_xq);
    cudaGetSymbolAddress((void**)&w16,   g_w16);
    cudaGetSymbolAddress((void**)&bias,  g_bias);

    // sA + sB + sStage + alpha
    const int SM128 = (64 * 136 + 128 * 136) * 2 + 64 * 136 * 2 + 1024;  // 70,656 B
    const int SM64  = (64 * 72  + 128 * 72)  * 2 + 64 * 136 * 2 + 1024;  // 46,080 B
    cudaFuncSetAttribute(gemm_mma<128, 128>, cudaFuncAttributeMaxDynamicSharedMemorySize, SM128);
    cudaFuncSetAttribute(gemm_mma<128, 64>,  cudaFuncAttributeMaxDynamicSharedMemorySize, SM128);
    cudaFuncSetAttribute(gemm_mma<64, 64>,   cudaFuncAttributeMaxDynamicSharedMemorySize, SM64);

    const int WTOT = 2 * 1152 * 128 + 1152 * 64;
    convert_w_all<<<(WTOT + 255) / 256, 256>>>(Wm2, bm2, Ws2, bs2,
                                               Wm3, bm3, Ws3, bs3,
                                               Wm4, bm4, Ws4, bs4, w16, bias);

    // Layer 1
    alpha1<<<NUMNODES / 32, 256>>>(nodes, Wm1, bm1, att1);
    out1<<<NUMNODES / 32, 256>>>(nodes, Wm1, bm1, Ws1, bs1, xq);

    const dim3 GG(NUMNODES / 64, 5);

    // Layer 2: K=128, C=128
    gemm_mma<128, 128><<<GG, 256, SM128>>>(xq, w16 + 0 * WSLOT,
                                           bias + 0 * 1152, att2, ymsg, yself);
    agg2h<128, 8, true, true, false><<<NUMNODES / 8, 256>>>(ymsg, yself, nullptr, xq);

    // Layer 3: K=128, C=64
    gemm_mma<128, 64><<<GG, 256, SM128>>>(xq, w16 + 1 * WSLOT,
                                          bias + 1 * 1152, att3, ymsg, yself);
    agg2h<64, 16, true, true, false><<<NUMNODES / 16, 256>>>(ymsg, yself, nullptr, xq);

    // Layer 4: K=64, C=64
    gemm_mma<64, 64><<<GG, 256, SM64>>>(xq, w16 + 2 * WSLOT,
                                        bias + 2 * 1152, att4, ymsg, yself);
    agg2h<64, 16, true, false, true><<<NUMNODES / 16, 256>>>(ymsg, yself, bufB, nullptr);

    // Layer 5 (small, fp32) — reuse yself as stride-64 scratch
    msg5<<<NUMNODES / 8, 256>>>(bufB, Wm5, bm5, Ws5, bs5, att5, yself);
    agg5<<<NUMNODES / 32, 256>>>(yself, bufA);

    final_k<<<1, 1024>>>(bufA, Wc, bc, (float*)d_out, out_size);
}